// round 7
// baseline (speedup 1.0000x reference)
#include <cuda_runtime.h>
#include <math_constants.h>

#define NN 100000
#define NE 1600000
#define IND 128
#define OUTD 64

#define SCAN_ELEMS 1024                       // per block (256 thr x 4)
#define NBLK ((NN + SCAN_ELEMS - 1) / SCAN_ELEMS)   // 98

// ---- scratch (static device globals; no allocation) ----
__device__ __align__(16) float g_z[(size_t)NN * OUTD];     // 25.6 MB
__device__ __align__(16) float g_ssrc[NN];
__device__ __align__(16) float g_sdst[NN];
__device__ __align__(16) int   g_deg[NN];
__device__ __align__(16) int   g_off[NN];
__device__ __align__(16) int   g_cur[NN];
__device__ __align__(16) unsigned long long g_epack[NE];   // 12.8 MB: (e_bits<<32)|src
__device__ int g_flagval[NBLK];                             // scan lookback: total+1, 0=unpublished

// ============================================================
// K1: z = h @ W^T  (64x64 tile, 4x4/thread) + fused score
//     epilogue (s_src = z@a[:64], s_dst = z@a[64:]) + deg=0
// ============================================================
__global__ __launch_bounds__(256) void k_gemm(const float* __restrict__ h,
                                              const float* __restrict__ W,
                                              const float* __restrict__ a) {
    __shared__ __align__(16) float hs[32][68];  // hs[k][node]
    __shared__ __align__(16) float ws[32][68];  // ws[k][out] = W[out][k]

    const int tx = threadIdx.x & 15;        // out tile (x4)
    const int ty = threadIdx.x >> 4;        // node tile (x4)
    const int node0 = blockIdx.x * 64;

    // zero deg for this block's nodes
    if (threadIdx.x < 64) {
        int gn = node0 + threadIdx.x;
        if (gn < NN) g_deg[gn] = 0;
    }

    float acc[4][4];
#pragma unroll
    for (int i = 0; i < 4; i++)
#pragma unroll
        for (int j = 0; j < 4; j++) acc[i][j] = 0.f;

    for (int k0 = 0; k0 < IND; k0 += 32) {
        const int r  = threadIdx.x >> 2;            // 0..63
        const int kb = (threadIdx.x & 3) * 8;       // k offset in tile
        {
            int gn = node0 + r;
            float4 v0 = make_float4(0.f, 0.f, 0.f, 0.f), v1 = v0;
            if (gn < NN) {
                const float4* hp = reinterpret_cast<const float4*>(h + (size_t)gn * IND + k0 + kb);
                v0 = hp[0]; v1 = hp[1];
            }
            hs[kb + 0][r] = v0.x; hs[kb + 1][r] = v0.y; hs[kb + 2][r] = v0.z; hs[kb + 3][r] = v0.w;
            hs[kb + 4][r] = v1.x; hs[kb + 5][r] = v1.y; hs[kb + 6][r] = v1.z; hs[kb + 7][r] = v1.w;

            const float4* wp = reinterpret_cast<const float4*>(W + (size_t)r * IND + k0 + kb);
            float4 w0 = wp[0], w1 = wp[1];
            ws[kb + 0][r] = w0.x; ws[kb + 1][r] = w0.y; ws[kb + 2][r] = w0.z; ws[kb + 3][r] = w0.w;
            ws[kb + 4][r] = w1.x; ws[kb + 5][r] = w1.y; ws[kb + 6][r] = w1.z; ws[kb + 7][r] = w1.w;
        }
        __syncthreads();
#pragma unroll
        for (int kk = 0; kk < 32; kk++) {
            float4 av = *reinterpret_cast<const float4*>(&hs[kk][ty * 4]);
            float4 bv = *reinterpret_cast<const float4*>(&ws[kk][tx * 4]);
            float aa[4] = {av.x, av.y, av.z, av.w};
            float bb[4] = {bv.x, bv.y, bv.z, bv.w};
#pragma unroll
            for (int i = 0; i < 4; i++)
#pragma unroll
                for (int j = 0; j < 4; j++) acc[i][j] += aa[i] * bb[j];
        }
        __syncthreads();
    }

    // store z tile
#pragma unroll
    for (int i = 0; i < 4; i++) {
        int gn = node0 + ty * 4 + i;
        if (gn < NN) {
            float4 v = make_float4(acc[i][0], acc[i][1], acc[i][2], acc[i][3]);
            *reinterpret_cast<float4*>(&g_z[(size_t)gn * OUTD + tx * 4]) = v;
        }
    }

    // fused score epilogue: reduce across the 16 tx threads (width-16 shuffle)
    float as[4], ad[4];
#pragma unroll
    for (int j = 0; j < 4; j++) {
        as[j] = __ldg(&a[tx * 4 + j]);
        ad[j] = __ldg(&a[64 + tx * 4 + j]);
    }
#pragma unroll
    for (int i = 0; i < 4; i++) {
        float ps = acc[i][0] * as[0] + acc[i][1] * as[1] + acc[i][2] * as[2] + acc[i][3] * as[3];
        float pd = acc[i][0] * ad[0] + acc[i][1] * ad[1] + acc[i][2] * ad[2] + acc[i][3] * ad[3];
#pragma unroll
        for (int o = 8; o > 0; o >>= 1) {
            ps += __shfl_down_sync(0xffffffffu, ps, o, 16);
            pd += __shfl_down_sync(0xffffffffu, pd, o, 16);
        }
        if (tx == 0) {
            int gn = node0 + ty * 4 + i;
            if (gn < NN) { g_ssrc[gn] = ps; g_sdst[gn] = pd; }
        }
    }
}

// ============================================================
// K2: dst-degree histogram (int4 vectorized) + reset scan flags
// ============================================================
__global__ __launch_bounds__(256) void k_hist(const int* __restrict__ dst) {
    int t = blockIdx.x * blockDim.x + threadIdx.x;
    if (t < NBLK) g_flagval[t] = 0;           // reset lookback state (scan runs strictly later)
    if (t * 4 >= NE) return;
    int4 d4 = reinterpret_cast<const int4*>(dst)[t];
    atomicAdd(&g_deg[d4.x], 1);
    atomicAdd(&g_deg[d4.y], 1);
    atomicAdd(&g_deg[d4.z], 1);
    atomicAdd(&g_deg[d4.w], 1);
}

// ============================================================
// K3: single-kernel exclusive scan with parallel lookback.
//     98 blocks (< 148 SMs, all co-resident). Each block publishes
//     its total+1 as one word; threads t<bid poll predecessors in
//     parallel and block-reduce the exclusive base.
// ============================================================
__global__ __launch_bounds__(256) void k_scan() {
    __shared__ int wsum[8];
    __shared__ int wred[8];
    __shared__ int s_base;
    const int bid  = blockIdx.x;
    const int lane = threadIdx.x & 31, wid = threadIdx.x >> 5;
    const int idx  = bid * SCAN_ELEMS + threadIdx.x * 4;

    int v[4];
    if (idx + 3 < NN) {
        int4 d = *reinterpret_cast<const int4*>(&g_deg[idx]);
        v[0] = d.x; v[1] = d.y; v[2] = d.z; v[3] = d.w;
    } else {
#pragma unroll
        for (int k = 0; k < 4; k++) v[k] = (idx + k < NN) ? g_deg[idx + k] : 0;
    }
    const int tot = v[0] + v[1] + v[2] + v[3];

    // warp inclusive scan of per-thread totals
    int x = tot;
#pragma unroll
    for (int o = 1; o < 32; o <<= 1) {
        int t = __shfl_up_sync(0xffffffffu, x, o);
        if (lane >= o) x += t;
    }
    if (lane == 31) wsum[wid] = x;
    __syncthreads();
    if (threadIdx.x < 32) {
        int w = (threadIdx.x < 8) ? wsum[threadIdx.x] : 0;
#pragma unroll
        for (int o = 1; o < 8; o <<= 1) {
            int t = __shfl_up_sync(0xffffffffu, w, o);
            if (threadIdx.x >= (unsigned)o) w += t;
        }
        if (threadIdx.x < 8) wsum[threadIdx.x] = w;   // inclusive warp prefixes
    }
    __syncthreads();

    // publish this block's total (value+1 doubles as the ready flag)
    if (threadIdx.x == 0)
        ((volatile int*)g_flagval)[bid] = wsum[7] + 1;

    // parallel lookback: thread t polls predecessor t
    int pre = 0;
    if ((int)threadIdx.x < bid) {
        volatile int* fv = g_flagval;
        int f;
        do { f = fv[threadIdx.x]; } while (f == 0);
        pre = f - 1;
    }
    // block reduce of pre
#pragma unroll
    for (int o = 16; o > 0; o >>= 1) pre += __shfl_down_sync(0xffffffffu, pre, o);
    if (lane == 0) wred[wid] = pre;
    __syncthreads();
    if (threadIdx.x < 32) {
        int r = (threadIdx.x < 8) ? wred[threadIdx.x] : 0;
#pragma unroll
        for (int o = 4; o > 0; o >>= 1) r += __shfl_down_sync(0xffffffffu, r, o);
        if (threadIdx.x == 0) s_base = r;
    }
    __syncthreads();

    int run = s_base + ((wid > 0) ? wsum[wid - 1] : 0) + (x - tot);
#pragma unroll
    for (int k = 0; k < 4; k++) {
        if (idx + k < NN) { g_off[idx + k] = run; g_cur[idx + k] = run; }
        run += v[k];
    }
}

// ============================================================
// K4: CSR scatter; recompute edge score inline, packed 8B record
// ============================================================
__global__ __launch_bounds__(256) void k_scatter(const int* __restrict__ src,
                                                 const int* __restrict__ dst) {
    int t = blockIdx.x * blockDim.x + threadIdx.x;
    if (t * 4 >= NE) return;
    int4 s4 = reinterpret_cast<const int4*>(src)[t];
    int4 d4 = reinterpret_cast<const int4*>(dst)[t];
    int ss[4] = {s4.x, s4.y, s4.z, s4.w};
    int dd[4] = {d4.x, d4.y, d4.z, d4.w};
#pragma unroll
    for (int k = 0; k < 4; k++) {
        float v = g_ssrc[ss[k]] + g_sdst[dd[k]];
        float e = v > 0.f ? v : 0.01f * v;
        int p = atomicAdd(&g_cur[dd[k]], 1);
        g_epack[p] = ((unsigned long long)__float_as_uint(e) << 32) | (unsigned)ss[k];
    }
}

// ============================================================
// K5: per-dst gather-reduce: softmax (no max shift; scores O(1))
//     + weighted sum + elu. One warp per node; lane = cols
//     (2*lane, 2*lane+1) via float2; 4x unrolled edge loop.
// ============================================================
__global__ __launch_bounds__(256) void k_aggr(float* __restrict__ out) {
    int node = blockIdx.x * 8 + (threadIdx.x >> 5);
    int lane = threadIdx.x & 31;
    if (node >= NN) return;

    int start = g_off[node];
    int dg    = g_deg[node];
    float2* op = reinterpret_cast<float2*>(out + (size_t)node * OUTD);

    if (dg == 0) { op[lane] = make_float2(0.f, 0.f); return; }

    float ax = 0.f, ay = 0.f, denom = 0.f;
    int j = 0;
    for (; j + 3 < dg; j += 4) {
        unsigned long long p0 = __ldg(&g_epack[start + j]);
        unsigned long long p1 = __ldg(&g_epack[start + j + 1]);
        unsigned long long p2 = __ldg(&g_epack[start + j + 2]);
        unsigned long long p3 = __ldg(&g_epack[start + j + 3]);
        int s0 = (int)(unsigned)p0, s1 = (int)(unsigned)p1;
        int s2 = (int)(unsigned)p2, s3 = (int)(unsigned)p3;
        float x0 = __expf(__uint_as_float((unsigned)(p0 >> 32)));
        float x1 = __expf(__uint_as_float((unsigned)(p1 >> 32)));
        float x2 = __expf(__uint_as_float((unsigned)(p2 >> 32)));
        float x3 = __expf(__uint_as_float((unsigned)(p3 >> 32)));
        float2 v0 = __ldg(&reinterpret_cast<const float2*>(&g_z[(size_t)s0 * OUTD])[lane]);
        float2 v1 = __ldg(&reinterpret_cast<const float2*>(&g_z[(size_t)s1 * OUTD])[lane]);
        float2 v2 = __ldg(&reinterpret_cast<const float2*>(&g_z[(size_t)s2 * OUTD])[lane]);
        float2 v3 = __ldg(&reinterpret_cast<const float2*>(&g_z[(size_t)s3 * OUTD])[lane]);
        denom += (x0 + x1) + (x2 + x3);
        ax += x0 * v0.x + x1 * v1.x + x2 * v2.x + x3 * v3.x;
        ay += x0 * v0.y + x1 * v1.y + x2 * v2.y + x3 * v3.y;
    }
    for (; j < dg; j++) {
        unsigned long long pk = __ldg(&g_epack[start + j]);
        int s = (int)(unsigned)pk;
        float xv = __expf(__uint_as_float((unsigned)(pk >> 32)));
        float2 zv = __ldg(&reinterpret_cast<const float2*>(&g_z[(size_t)s * OUTD])[lane]);
        denom += xv;
        ax += xv * zv.x;
        ay += xv * zv.y;
    }

    float inv = 1.0f / denom;     // denom > 0 (all terms > 0)
    float ox = ax * inv, oy = ay * inv;
    op[lane] = make_float2(ox > 0.f ? ox : (__expf(ox) - 1.0f),
                           oy > 0.f ? oy : (__expf(oy) - 1.0f));
}

// ============================================================
extern "C" void kernel_launch(void* const* d_in, const int* in_sizes, int n_in,
                              void* d_out, int out_size) {
    const float* h   = (const float*)d_in[0];
    const int*   src = (const int*)d_in[1];
    const int*   dst = (const int*)d_in[2];
    const float* W   = (const float*)d_in[3];
    const float* a   = (const float*)d_in[4];
    float* out = (float*)d_out;

    k_gemm   <<<(NN + 63) / 64, 256>>>(h, W, a);
    k_hist   <<<(NE / 4 + 255) / 256, 256>>>(dst);
    k_scan   <<<NBLK, 256>>>();
    k_scatter<<<(NE / 4 + 255) / 256, 256>>>(src, dst);
    k_aggr   <<<(NN + 7) / 8, 256>>>(out);
}

// round 9
// speedup vs baseline: 1.3041x; 1.3041x over previous
#include <cuda_runtime.h>
#include <math_constants.h>

#define NN 100000
#define NE 1600000
#define IND 128
#define OUTD 64

#define SCAN_ELEMS 1024                       // per block (256 thr x 4)
#define NBLK ((NN + SCAN_ELEMS - 1) / SCAN_ELEMS)   // 98

// ---- scratch (static device globals; no allocation) ----
__device__ __align__(16) float g_z[(size_t)NN * OUTD];     // 25.6 MB
__device__ __align__(16) float g_ssrc[NN];
__device__ __align__(16) float g_sdst[NN];
__device__ __align__(16) int   g_deg[NN];
__device__ __align__(16) int   g_off[NN];
__device__ __align__(16) int   g_cur[NN];
__device__ __align__(16) int   g_csrc[NE];                 // 6.4 MB
__device__ __align__(16) float g_ce[NE];                   // 6.4 MB
__device__ int g_flagval[NBLK];                            // scan lookback: total+1, 0=unpublished

// ============================================================
// K1: z = h @ W^T  (64x64 tile, 4x4/thread) + fused score
//     epilogue (s_src = z@a[:64], s_dst = z@a[64:]) + deg=0
// ============================================================
__global__ __launch_bounds__(256) void k_gemm(const float* __restrict__ h,
                                              const float* __restrict__ W,
                                              const float* __restrict__ a) {
    __shared__ __align__(16) float hs[32][68];  // hs[k][node]
    __shared__ __align__(16) float ws[32][68];  // ws[k][out] = W[out][k]

    const int tx = threadIdx.x & 15;        // out tile (x4)
    const int ty = threadIdx.x >> 4;        // node tile (x4)
    const int node0 = blockIdx.x * 64;

    // zero deg for this block's nodes
    if (threadIdx.x < 64) {
        int gn = node0 + threadIdx.x;
        if (gn < NN) g_deg[gn] = 0;
    }

    float acc[4][4];
#pragma unroll
    for (int i = 0; i < 4; i++)
#pragma unroll
        for (int j = 0; j < 4; j++) acc[i][j] = 0.f;

    for (int k0 = 0; k0 < IND; k0 += 32) {
        const int r  = threadIdx.x >> 2;            // 0..63
        const int kb = (threadIdx.x & 3) * 8;       // k offset in tile
        {
            int gn = node0 + r;
            float4 v0 = make_float4(0.f, 0.f, 0.f, 0.f), v1 = v0;
            if (gn < NN) {
                const float4* hp = reinterpret_cast<const float4*>(h + (size_t)gn * IND + k0 + kb);
                v0 = hp[0]; v1 = hp[1];
            }
            hs[kb + 0][r] = v0.x; hs[kb + 1][r] = v0.y; hs[kb + 2][r] = v0.z; hs[kb + 3][r] = v0.w;
            hs[kb + 4][r] = v1.x; hs[kb + 5][r] = v1.y; hs[kb + 6][r] = v1.z; hs[kb + 7][r] = v1.w;

            const float4* wp = reinterpret_cast<const float4*>(W + (size_t)r * IND + k0 + kb);
            float4 w0 = wp[0], w1 = wp[1];
            ws[kb + 0][r] = w0.x; ws[kb + 1][r] = w0.y; ws[kb + 2][r] = w0.z; ws[kb + 3][r] = w0.w;
            ws[kb + 4][r] = w1.x; ws[kb + 5][r] = w1.y; ws[kb + 6][r] = w1.z; ws[kb + 7][r] = w1.w;
        }
        __syncthreads();
#pragma unroll
        for (int kk = 0; kk < 32; kk++) {
            float4 av = *reinterpret_cast<const float4*>(&hs[kk][ty * 4]);
            float4 bv = *reinterpret_cast<const float4*>(&ws[kk][tx * 4]);
            float aa[4] = {av.x, av.y, av.z, av.w};
            float bb[4] = {bv.x, bv.y, bv.z, bv.w};
#pragma unroll
            for (int i = 0; i < 4; i++)
#pragma unroll
                for (int j = 0; j < 4; j++) acc[i][j] += aa[i] * bb[j];
        }
        __syncthreads();
    }

    // store z tile
#pragma unroll
    for (int i = 0; i < 4; i++) {
        int gn = node0 + ty * 4 + i;
        if (gn < NN) {
            float4 v = make_float4(acc[i][0], acc[i][1], acc[i][2], acc[i][3]);
            *reinterpret_cast<float4*>(&g_z[(size_t)gn * OUTD + tx * 4]) = v;
        }
    }

    // fused score epilogue: reduce across the 16 tx threads (width-16 shuffle)
    float as[4], ad[4];
#pragma unroll
    for (int j = 0; j < 4; j++) {
        as[j] = __ldg(&a[tx * 4 + j]);
        ad[j] = __ldg(&a[64 + tx * 4 + j]);
    }
#pragma unroll
    for (int i = 0; i < 4; i++) {
        float ps = acc[i][0] * as[0] + acc[i][1] * as[1] + acc[i][2] * as[2] + acc[i][3] * as[3];
        float pd = acc[i][0] * ad[0] + acc[i][1] * ad[1] + acc[i][2] * ad[2] + acc[i][3] * ad[3];
#pragma unroll
        for (int o = 8; o > 0; o >>= 1) {
            ps += __shfl_down_sync(0xffffffffu, ps, o, 16);
            pd += __shfl_down_sync(0xffffffffu, pd, o, 16);
        }
        if (tx == 0) {
            int gn = node0 + ty * 4 + i;
            if (gn < NN) { g_ssrc[gn] = ps; g_sdst[gn] = pd; }
        }
    }
}

// ============================================================
// K2: dst-degree histogram (int4 vectorized) + reset scan flags
// ============================================================
__global__ __launch_bounds__(256) void k_hist(const int* __restrict__ dst) {
    int t = blockIdx.x * blockDim.x + threadIdx.x;
    if (t < NBLK) g_flagval[t] = 0;           // reset lookback state (scan runs strictly later)
    if (t * 4 >= NE) return;
    int4 d4 = reinterpret_cast<const int4*>(dst)[t];
    atomicAdd(&g_deg[d4.x], 1);
    atomicAdd(&g_deg[d4.y], 1);
    atomicAdd(&g_deg[d4.z], 1);
    atomicAdd(&g_deg[d4.w], 1);
}

// ============================================================
// K3: single-kernel exclusive scan with parallel lookback.
//     98 blocks (< 148 SMs, all co-resident). Each block publishes
//     its total+1 in one word; threads t<bid poll predecessors in
//     parallel and block-reduce the exclusive base.
// ============================================================
__global__ __launch_bounds__(256) void k_scan() {
    __shared__ int wsum[8];
    __shared__ int wred[8];
    __shared__ int s_base;
    const int bid  = blockIdx.x;
    const int lane = threadIdx.x & 31, wid = threadIdx.x >> 5;
    const int idx  = bid * SCAN_ELEMS + threadIdx.x * 4;

    int v[4];
    if (idx + 3 < NN) {
        int4 d = *reinterpret_cast<const int4*>(&g_deg[idx]);
        v[0] = d.x; v[1] = d.y; v[2] = d.z; v[3] = d.w;
    } else {
#pragma unroll
        for (int k = 0; k < 4; k++) v[k] = (idx + k < NN) ? g_deg[idx + k] : 0;
    }
    const int tot = v[0] + v[1] + v[2] + v[3];

    // warp inclusive scan of per-thread totals
    int x = tot;
#pragma unroll
    for (int o = 1; o < 32; o <<= 1) {
        int t = __shfl_up_sync(0xffffffffu, x, o);
        if (lane >= o) x += t;
    }
    if (lane == 31) wsum[wid] = x;
    __syncthreads();
    if (threadIdx.x < 32) {
        int w = (threadIdx.x < 8) ? wsum[threadIdx.x] : 0;
#pragma unroll
        for (int o = 1; o < 8; o <<= 1) {
            int t = __shfl_up_sync(0xffffffffu, w, o);
            if (threadIdx.x >= (unsigned)o) w += t;
        }
        if (threadIdx.x < 8) wsum[threadIdx.x] = w;   // inclusive warp prefixes
    }
    __syncthreads();

    // publish this block's total (value+1 doubles as the ready flag)
    if (threadIdx.x == 0)
        ((volatile int*)g_flagval)[bid] = wsum[7] + 1;

    // parallel lookback: thread t polls predecessor t
    int pre = 0;
    if ((int)threadIdx.x < bid) {
        volatile int* fv = g_flagval;
        int f;
        do { f = fv[threadIdx.x]; } while (f == 0);
        pre = f - 1;
    }
    // block reduce of pre
#pragma unroll
    for (int o = 16; o > 0; o >>= 1) pre += __shfl_down_sync(0xffffffffu, pre, o);
    if (lane == 0) wred[wid] = pre;
    __syncthreads();
    if (threadIdx.x < 32) {
        int r = (threadIdx.x < 8) ? wred[threadIdx.x] : 0;
#pragma unroll
        for (int o = 4; o > 0; o >>= 1) r += __shfl_down_sync(0xffffffffu, r, o);
        if (threadIdx.x == 0) s_base = r;
    }
    __syncthreads();

    int run = s_base + ((wid > 0) ? wsum[wid - 1] : 0) + (x - tot);
#pragma unroll
    for (int k = 0; k < 4; k++) {
        if (idx + k < NN) { g_off[idx + k] = run; g_cur[idx + k] = run; }
        run += v[k];
    }
}

// ============================================================
// K4: CSR scatter; software-pipelined phases so all long-latency
//     ops (8 gathers, then 4 atomics) are in flight together.
//     Two 4B stores per edge (separate arrays — round-4 layout).
// ============================================================
__global__ __launch_bounds__(256) void k_scatter(const int* __restrict__ src,
                                                 const int* __restrict__ dst) {
    int t = blockIdx.x * blockDim.x + threadIdx.x;
    if (t * 4 >= NE) return;
    int4 s4 = reinterpret_cast<const int4*>(src)[t];
    int4 d4 = reinterpret_cast<const int4*>(dst)[t];
    int ss[4] = {s4.x, s4.y, s4.z, s4.w};
    int dd[4] = {d4.x, d4.y, d4.z, d4.w};

    // phase 1: issue all 8 random gathers
    float sv[4], dv[4];
#pragma unroll
    for (int k = 0; k < 4; k++) sv[k] = __ldg(&g_ssrc[ss[k]]);
#pragma unroll
    for (int k = 0; k < 4; k++) dv[k] = __ldg(&g_sdst[dd[k]]);

    // phase 2: issue all 4 atomics (independent of gathers)
    int p[4];
#pragma unroll
    for (int k = 0; k < 4; k++) p[k] = atomicAdd(&g_cur[dd[k]], 1);

    // phase 3: compute + scattered stores
#pragma unroll
    for (int k = 0; k < 4; k++) {
        float v = sv[k] + dv[k];
        float e = v > 0.f ? v : 0.01f * v;
        g_csrc[p[k]] = ss[k];
        g_ce[p[k]]   = e;
    }
}

// ============================================================
// K5: per-dst gather-reduce: softmax (no max shift; scores O(1)
//     so exp is safe; the shift cancels exactly in the ratio)
//     + weighted sum + elu. One warp per node; lane covers cols
//     (lane, lane+32); 4x unrolled edge loop for MLP.
// ============================================================
__global__ __launch_bounds__(256) void k_aggr(float* __restrict__ out) {
    int node = blockIdx.x * 8 + (threadIdx.x >> 5);
    int lane = threadIdx.x & 31;
    if (node >= NN) return;

    int start = g_off[node];
    int dg    = g_deg[node];

    if (dg == 0) {
        out[(size_t)node * OUTD + lane] = 0.f;
        out[(size_t)node * OUTD + 32 + lane] = 0.f;
        return;
    }

    float acc0 = 0.f, acc1 = 0.f, denom = 0.f;
    int j = 0;
    for (; j + 3 < dg; j += 4) {
        int e0 = start + j, e1 = e0 + 1, e2 = e0 + 2, e3 = e0 + 3;
        float ev0 = g_ce[e0], ev1 = g_ce[e1], ev2 = g_ce[e2], ev3 = g_ce[e3];
        int   s0 = g_csrc[e0], s1 = g_csrc[e1], s2 = g_csrc[e2], s3 = g_csrc[e3];
        const float* zp0 = &g_z[(size_t)s0 * OUTD];
        const float* zp1 = &g_z[(size_t)s1 * OUTD];
        const float* zp2 = &g_z[(size_t)s2 * OUTD];
        const float* zp3 = &g_z[(size_t)s3 * OUTD];
        float a00 = zp0[lane], a01 = zp0[32 + lane];
        float a10 = zp1[lane], a11 = zp1[32 + lane];
        float a20 = zp2[lane], a21 = zp2[32 + lane];
        float a30 = zp3[lane], a31 = zp3[32 + lane];
        float x0 = __expf(ev0), x1 = __expf(ev1);
        float x2 = __expf(ev2), x3 = __expf(ev3);
        denom += (x0 + x1) + (x2 + x3);
        acc0 += x0 * a00 + x1 * a10 + x2 * a20 + x3 * a30;
        acc1 += x0 * a01 + x1 * a11 + x2 * a21 + x3 * a31;
    }
    for (; j < dg; j++) {
        int eid = start + j;
        float x = __expf(g_ce[eid]);
        const float* zp = &g_z[(size_t)g_csrc[eid] * OUTD];
        denom += x;
        acc0 += x * zp[lane];
        acc1 += x * zp[32 + lane];
    }

    float inv = 1.0f / denom;     // denom > 0 (all terms > 0)
    float o0 = acc0 * inv;
    float o1 = acc1 * inv;
    out[(size_t)node * OUTD + lane]      = o0 > 0.f ? o0 : (__expf(o0) - 1.0f);
    out[(size_t)node * OUTD + 32 + lane] = o1 > 0.f ? o1 : (__expf(o1) - 1.0f);
}

// ============================================================
extern "C" void kernel_launch(void* const* d_in, const int* in_sizes, int n_in,
                              void* d_out, int out_size) {
    const float* h   = (const float*)d_in[0];
    const int*   src = (const int*)d_in[1];
    const int*   dst = (const int*)d_in[2];
    const float* W   = (const float*)d_in[3];
    const float* a   = (const float*)d_in[4];
    float* out = (float*)d_out;

    k_gemm   <<<(NN + 63) / 64, 256>>>(h, W, a);
    k_hist   <<<(NE / 4 + 255) / 256, 256>>>(dst);
    k_scan   <<<NBLK, 256>>>();
    k_scatter<<<(NE / 4 + 255) / 256, 256>>>(src, dst);
    k_aggr   <<<(NN + 7) / 8, 256>>>(out);
}

// round 10
// speedup vs baseline: 1.4031x; 1.0759x over previous
#include <cuda_runtime.h>
#include <math_constants.h>

#define NN 100000
#define NE 1600000
#define IND 128
#define OUTD 64

#define SCAN_ELEMS 1024                       // per block (256 thr x 4)
#define NBLK ((NN + SCAN_ELEMS - 1) / SCAN_ELEMS)   // 98

// ---- scratch (static device globals; no allocation) ----
__device__ __align__(16) float g_z[(size_t)NN * OUTD];     // 25.6 MB
__device__ __align__(16) float g_ssrc[NN];
__device__ __align__(16) float g_sdst[NN];
__device__ __align__(16) int   g_deg[NN];
__device__ __align__(16) int   g_off[NN];
__device__ __align__(16) int   g_rank[NE];                 // 6.4 MB: rank of edge within its dst segment
__device__ __align__(16) int   g_csrc[NE];                 // 6.4 MB: CSR src ids
__device__ int g_flagval[NBLK];                            // scan lookback: total+1, 0=unpublished

// ============================================================
// K1: z = h @ W^T  (64x64 tile, 4x4/thread) + fused score
//     epilogue (s_src = z@a[:64], s_dst = z@a[64:]) + deg=0
// ============================================================
__global__ __launch_bounds__(256) void k_gemm(const float* __restrict__ h,
                                              const float* __restrict__ W,
                                              const float* __restrict__ a) {
    __shared__ __align__(16) float hs[32][68];  // hs[k][node]
    __shared__ __align__(16) float ws[32][68];  // ws[k][out] = W[out][k]

    const int tx = threadIdx.x & 15;        // out tile (x4)
    const int ty = threadIdx.x >> 4;        // node tile (x4)
    const int node0 = blockIdx.x * 64;

    // zero deg for this block's nodes
    if (threadIdx.x < 64) {
        int gn = node0 + threadIdx.x;
        if (gn < NN) g_deg[gn] = 0;
    }

    float acc[4][4];
#pragma unroll
    for (int i = 0; i < 4; i++)
#pragma unroll
        for (int j = 0; j < 4; j++) acc[i][j] = 0.f;

    for (int k0 = 0; k0 < IND; k0 += 32) {
        const int r  = threadIdx.x >> 2;            // 0..63
        const int kb = (threadIdx.x & 3) * 8;       // k offset in tile
        {
            int gn = node0 + r;
            float4 v0 = make_float4(0.f, 0.f, 0.f, 0.f), v1 = v0;
            if (gn < NN) {
                const float4* hp = reinterpret_cast<const float4*>(h + (size_t)gn * IND + k0 + kb);
                v0 = hp[0]; v1 = hp[1];
            }
            hs[kb + 0][r] = v0.x; hs[kb + 1][r] = v0.y; hs[kb + 2][r] = v0.z; hs[kb + 3][r] = v0.w;
            hs[kb + 4][r] = v1.x; hs[kb + 5][r] = v1.y; hs[kb + 6][r] = v1.z; hs[kb + 7][r] = v1.w;

            const float4* wp = reinterpret_cast<const float4*>(W + (size_t)r * IND + k0 + kb);
            float4 w0 = wp[0], w1 = wp[1];
            ws[kb + 0][r] = w0.x; ws[kb + 1][r] = w0.y; ws[kb + 2][r] = w0.z; ws[kb + 3][r] = w0.w;
            ws[kb + 4][r] = w1.x; ws[kb + 5][r] = w1.y; ws[kb + 6][r] = w1.z; ws[kb + 7][r] = w1.w;
        }
        __syncthreads();
#pragma unroll
        for (int kk = 0; kk < 32; kk++) {
            float4 av = *reinterpret_cast<const float4*>(&hs[kk][ty * 4]);
            float4 bv = *reinterpret_cast<const float4*>(&ws[kk][tx * 4]);
            float aa[4] = {av.x, av.y, av.z, av.w};
            float bb[4] = {bv.x, bv.y, bv.z, bv.w};
#pragma unroll
            for (int i = 0; i < 4; i++)
#pragma unroll
                for (int j = 0; j < 4; j++) acc[i][j] += aa[i] * bb[j];
        }
        __syncthreads();
    }

    // store z tile
#pragma unroll
    for (int i = 0; i < 4; i++) {
        int gn = node0 + ty * 4 + i;
        if (gn < NN) {
            float4 v = make_float4(acc[i][0], acc[i][1], acc[i][2], acc[i][3]);
            *reinterpret_cast<float4*>(&g_z[(size_t)gn * OUTD + tx * 4]) = v;
        }
    }

    // fused score epilogue: reduce across the 16 tx threads (width-16 shuffle)
    float as[4], ad[4];
#pragma unroll
    for (int j = 0; j < 4; j++) {
        as[j] = __ldg(&a[tx * 4 + j]);
        ad[j] = __ldg(&a[64 + tx * 4 + j]);
    }
#pragma unroll
    for (int i = 0; i < 4; i++) {
        float ps = acc[i][0] * as[0] + acc[i][1] * as[1] + acc[i][2] * as[2] + acc[i][3] * as[3];
        float pd = acc[i][0] * ad[0] + acc[i][1] * ad[1] + acc[i][2] * ad[2] + acc[i][3] * ad[3];
#pragma unroll
        for (int o = 8; o > 0; o >>= 1) {
            ps += __shfl_down_sync(0xffffffffu, ps, o, 16);
            pd += __shfl_down_sync(0xffffffffu, pd, o, 16);
        }
        if (tx == 0) {
            int gn = node0 + ty * 4 + i;
            if (gn < NN) { g_ssrc[gn] = ps; g_sdst[gn] = pd; }
        }
    }
}

// ============================================================
// K2: dst-degree histogram; the atomic's return value IS the
//     edge's rank within its dst segment -> store it coalesced.
//     Also resets scan lookback flags.
// ============================================================
__global__ __launch_bounds__(256) void k_hist(const int* __restrict__ dst) {
    int t = blockIdx.x * blockDim.x + threadIdx.x;
    if (t < NBLK) g_flagval[t] = 0;           // reset lookback state (scan runs strictly later)
    if (t * 4 >= NE) return;
    int4 d4 = reinterpret_cast<const int4*>(dst)[t];
    int4 r4;
    r4.x = atomicAdd(&g_deg[d4.x], 1);
    r4.y = atomicAdd(&g_deg[d4.y], 1);
    r4.z = atomicAdd(&g_deg[d4.z], 1);
    r4.w = atomicAdd(&g_deg[d4.w], 1);
    reinterpret_cast<int4*>(g_rank)[t] = r4;  // coalesced
}

// ============================================================
// K3: single-kernel exclusive scan with parallel lookback.
//     98 blocks (< 148 SMs, all co-resident). Each block publishes
//     its total+1 in one word; threads t<bid poll predecessors in
//     parallel and block-reduce the exclusive base.
// ============================================================
__global__ __launch_bounds__(256) void k_scan() {
    __shared__ int wsum[8];
    __shared__ int wred[8];
    __shared__ int s_base;
    const int bid  = blockIdx.x;
    const int lane = threadIdx.x & 31, wid = threadIdx.x >> 5;
    const int idx  = bid * SCAN_ELEMS + threadIdx.x * 4;

    int v[4];
    if (idx + 3 < NN) {
        int4 d = *reinterpret_cast<const int4*>(&g_deg[idx]);
        v[0] = d.x; v[1] = d.y; v[2] = d.z; v[3] = d.w;
    } else {
#pragma unroll
        for (int k = 0; k < 4; k++) v[k] = (idx + k < NN) ? g_deg[idx + k] : 0;
    }
    const int tot = v[0] + v[1] + v[2] + v[3];

    // warp inclusive scan of per-thread totals
    int x = tot;
#pragma unroll
    for (int o = 1; o < 32; o <<= 1) {
        int t = __shfl_up_sync(0xffffffffu, x, o);
        if (lane >= o) x += t;
    }
    if (lane == 31) wsum[wid] = x;
    __syncthreads();
    if (threadIdx.x < 32) {
        int w = (threadIdx.x < 8) ? wsum[threadIdx.x] : 0;
#pragma unroll
        for (int o = 1; o < 8; o <<= 1) {
            int t = __shfl_up_sync(0xffffffffu, w, o);
            if (threadIdx.x >= (unsigned)o) w += t;
        }
        if (threadIdx.x < 8) wsum[threadIdx.x] = w;   // inclusive warp prefixes
    }
    __syncthreads();

    // publish this block's total (value+1 doubles as the ready flag)
    if (threadIdx.x == 0)
        ((volatile int*)g_flagval)[bid] = wsum[7] + 1;

    // parallel lookback: thread t polls predecessor t
    int pre = 0;
    if ((int)threadIdx.x < bid) {
        volatile int* fv = g_flagval;
        int f;
        do { f = fv[threadIdx.x]; } while (f == 0);
        pre = f - 1;
    }
    // block reduce of pre
#pragma unroll
    for (int o = 16; o > 0; o >>= 1) pre += __shfl_down_sync(0xffffffffu, pre, o);
    if (lane == 0) wred[wid] = pre;
    __syncthreads();
    if (threadIdx.x < 32) {
        int r = (threadIdx.x < 8) ? wred[threadIdx.x] : 0;
#pragma unroll
        for (int o = 4; o > 0; o >>= 1) r += __shfl_down_sync(0xffffffffu, r, o);
        if (threadIdx.x == 0) s_base = r;
    }
    __syncthreads();

    int run = s_base + ((wid > 0) ? wsum[wid - 1] : 0) + (x - tot);
#pragma unroll
    for (int k = 0; k < 4; k++) {
        if (idx + k < NN) g_off[idx + k] = run;
        run += v[k];
    }
}

// ============================================================
// K4: CSR scatter — atomic-free. Slot = off[dst] + rank.
//     Per edge: coalesced src/dst/rank loads, one random 4B
//     gather (off, 400KB L2-resident), one random 4B store.
// ============================================================
__global__ __launch_bounds__(256) void k_scatter(const int* __restrict__ src,
                                                 const int* __restrict__ dst) {
    int t = blockIdx.x * blockDim.x + threadIdx.x;
    if (t * 4 >= NE) return;
    int4 s4 = reinterpret_cast<const int4*>(src)[t];
    int4 d4 = reinterpret_cast<const int4*>(dst)[t];
    int4 r4 = reinterpret_cast<const int4*>(g_rank)[t];
    int ss[4] = {s4.x, s4.y, s4.z, s4.w};
    int dd[4] = {d4.x, d4.y, d4.z, d4.w};
    int rr[4] = {r4.x, r4.y, r4.z, r4.w};

    int o[4];
#pragma unroll
    for (int k = 0; k < 4; k++) o[k] = __ldg(&g_off[dd[k]]);
#pragma unroll
    for (int k = 0; k < 4; k++) g_csrc[o[k] + rr[k]] = ss[k];
}

// ============================================================
// K5: per-dst gather-reduce. Edge score recomputed in place:
//     e = leaky(ssrc[s] + sdst[node]); sdst[node] is uniform per
//     warp, ssrc[s] is a broadcast gather (1 sector). Softmax
//     without max shift (scores O(1); shift cancels in ratio)
//     + weighted sum + elu. One warp per node; lane covers cols
//     (lane, lane+32); 4x unrolled edge loop for MLP.
// ============================================================
__global__ __launch_bounds__(256) void k_aggr(float* __restrict__ out) {
    int node = blockIdx.x * 8 + (threadIdx.x >> 5);
    int lane = threadIdx.x & 31;
    if (node >= NN) return;

    int start = g_off[node];
    int dg    = g_deg[node];

    if (dg == 0) {
        out[(size_t)node * OUTD + lane] = 0.f;
        out[(size_t)node * OUTD + 32 + lane] = 0.f;
        return;
    }

    const float sd = g_sdst[node];

    float acc0 = 0.f, acc1 = 0.f, denom = 0.f;
    int j = 0;
    for (; j + 3 < dg; j += 4) {
        int e0 = start + j;
        int s0 = g_csrc[e0], s1 = g_csrc[e0 + 1], s2 = g_csrc[e0 + 2], s3 = g_csrc[e0 + 3];
        float v0 = __ldg(&g_ssrc[s0]) + sd;
        float v1 = __ldg(&g_ssrc[s1]) + sd;
        float v2 = __ldg(&g_ssrc[s2]) + sd;
        float v3 = __ldg(&g_ssrc[s3]) + sd;
        const float* zp0 = &g_z[(size_t)s0 * OUTD];
        const float* zp1 = &g_z[(size_t)s1 * OUTD];
        const float* zp2 = &g_z[(size_t)s2 * OUTD];
        const float* zp3 = &g_z[(size_t)s3 * OUTD];
        float a00 = zp0[lane], a01 = zp0[32 + lane];
        float a10 = zp1[lane], a11 = zp1[32 + lane];
        float a20 = zp2[lane], a21 = zp2[32 + lane];
        float a30 = zp3[lane], a31 = zp3[32 + lane];
        float x0 = __expf(v0 > 0.f ? v0 : 0.01f * v0);
        float x1 = __expf(v1 > 0.f ? v1 : 0.01f * v1);
        float x2 = __expf(v2 > 0.f ? v2 : 0.01f * v2);
        float x3 = __expf(v3 > 0.f ? v3 : 0.01f * v3);
        denom += (x0 + x1) + (x2 + x3);
        acc0 += x0 * a00 + x1 * a10 + x2 * a20 + x3 * a30;
        acc1 += x0 * a01 + x1 * a11 + x2 * a21 + x3 * a31;
    }
    for (; j < dg; j++) {
        int s = g_csrc[start + j];
        float v = __ldg(&g_ssrc[s]) + sd;
        float x = __expf(v > 0.f ? v : 0.01f * v);
        const float* zp = &g_z[(size_t)s * OUTD];
        denom += x;
        acc0 += x * zp[lane];
        acc1 += x * zp[32 + lane];
    }

    float inv = 1.0f / denom;     // denom > 0 (all terms > 0)
    float o0 = acc0 * inv;
    float o1 = acc1 * inv;
    out[(size_t)node * OUTD + lane]      = o0 > 0.f ? o0 : (__expf(o0) - 1.0f);
    out[(size_t)node * OUTD + 32 + lane] = o1 > 0.f ? o1 : (__expf(o1) - 1.0f);
}

// ============================================================
extern "C" void kernel_launch(void* const* d_in, const int* in_sizes, int n_in,
                              void* d_out, int out_size) {
    const float* h   = (const float*)d_in[0];
    const int*   src = (const int*)d_in[1];
    const int*   dst = (const int*)d_in[2];
    const float* W   = (const float*)d_in[3];
    const float* a   = (const float*)d_in[4];
    float* out = (float*)d_out;

    k_gemm   <<<(NN + 63) / 64, 256>>>(h, W, a);
    k_hist   <<<(NE / 4 + 255) / 256, 256>>>(dst);
    k_scan   <<<NBLK, 256>>>();
    k_scatter<<<(NE / 4 + 255) / 256, 256>>>(src, dst);
    k_aggr   <<<(NN + 7) / 8, 256>>>(out);
}

// round 11
// speedup vs baseline: 1.4938x; 1.0647x over previous
#include <cuda_runtime.h>
#include <math_constants.h>

#define NN 100000
#define NE 1600000
#define IND 128
#define OUTD 64

#define SCAN_ELEMS 1024                       // per block (256 thr x 4)
#define NBLK ((NN + SCAN_ELEMS - 1) / SCAN_ELEMS)   // 98

// ---- scratch (static device globals; no allocation) ----
__device__ __align__(16) float g_z[(size_t)NN * OUTD];     // 25.6 MB
__device__ __align__(16) float g_ssrc[NN];
__device__ __align__(16) float g_sdst[NN];
__device__ __align__(16) int   g_deg[NN];
__device__ __align__(16) int   g_off[NN];
__device__ __align__(16) int   g_rank[NE];                 // 6.4 MB: rank of edge within its dst segment
__device__ __align__(16) int   g_csrc[NE];                 // 6.4 MB: CSR src ids
__device__ int g_flagval[NBLK];                            // scan lookback: total+1, 0=unpublished

// ============================================================
// K1: z = h @ W^T  (64x64 tile, 4x4/thread) + fused score
//     epilogue (s_src = z@a[:64], s_dst = z@a[64:])
// ============================================================
__global__ __launch_bounds__(256) void k_gemm(const float* __restrict__ h,
                                              const float* __restrict__ W,
                                              const float* __restrict__ a) {
    __shared__ __align__(16) float hs[32][68];  // hs[k][node]
    __shared__ __align__(16) float ws[32][68];  // ws[k][out] = W[out][k]

    const int tx = threadIdx.x & 15;        // out tile (x4)
    const int ty = threadIdx.x >> 4;        // node tile (x4)
    const int node0 = blockIdx.x * 64;

    float acc[4][4];
#pragma unroll
    for (int i = 0; i < 4; i++)
#pragma unroll
        for (int j = 0; j < 4; j++) acc[i][j] = 0.f;

    for (int k0 = 0; k0 < IND; k0 += 32) {
        const int r  = threadIdx.x >> 2;            // 0..63
        const int kb = (threadIdx.x & 3) * 8;       // k offset in tile
        {
            int gn = node0 + r;
            float4 v0 = make_float4(0.f, 0.f, 0.f, 0.f), v1 = v0;
            if (gn < NN) {
                const float4* hp = reinterpret_cast<const float4*>(h + (size_t)gn * IND + k0 + kb);
                v0 = hp[0]; v1 = hp[1];
            }
            hs[kb + 0][r] = v0.x; hs[kb + 1][r] = v0.y; hs[kb + 2][r] = v0.z; hs[kb + 3][r] = v0.w;
            hs[kb + 4][r] = v1.x; hs[kb + 5][r] = v1.y; hs[kb + 6][r] = v1.z; hs[kb + 7][r] = v1.w;

            const float4* wp = reinterpret_cast<const float4*>(W + (size_t)r * IND + k0 + kb);
            float4 w0 = wp[0], w1 = wp[1];
            ws[kb + 0][r] = w0.x; ws[kb + 1][r] = w0.y; ws[kb + 2][r] = w0.z; ws[kb + 3][r] = w0.w;
            ws[kb + 4][r] = w1.x; ws[kb + 5][r] = w1.y; ws[kb + 6][r] = w1.z; ws[kb + 7][r] = w1.w;
        }
        __syncthreads();
#pragma unroll
        for (int kk = 0; kk < 32; kk++) {
            float4 av = *reinterpret_cast<const float4*>(&hs[kk][ty * 4]);
            float4 bv = *reinterpret_cast<const float4*>(&ws[kk][tx * 4]);
            float aa[4] = {av.x, av.y, av.z, av.w};
            float bb[4] = {bv.x, bv.y, bv.z, bv.w};
#pragma unroll
            for (int i = 0; i < 4; i++)
#pragma unroll
                for (int j = 0; j < 4; j++) acc[i][j] += aa[i] * bb[j];
        }
        __syncthreads();
    }

    // store z tile
#pragma unroll
    for (int i = 0; i < 4; i++) {
        int gn = node0 + ty * 4 + i;
        if (gn < NN) {
            float4 v = make_float4(acc[i][0], acc[i][1], acc[i][2], acc[i][3]);
            *reinterpret_cast<float4*>(&g_z[(size_t)gn * OUTD + tx * 4]) = v;
        }
    }

    // fused score epilogue: reduce across the 16 tx threads (width-16 shuffle)
    float as[4], ad[4];
#pragma unroll
    for (int j = 0; j < 4; j++) {
        as[j] = __ldg(&a[tx * 4 + j]);
        ad[j] = __ldg(&a[64 + tx * 4 + j]);
    }
#pragma unroll
    for (int i = 0; i < 4; i++) {
        float ps = acc[i][0] * as[0] + acc[i][1] * as[1] + acc[i][2] * as[2] + acc[i][3] * as[3];
        float pd = acc[i][0] * ad[0] + acc[i][1] * ad[1] + acc[i][2] * ad[2] + acc[i][3] * ad[3];
#pragma unroll
        for (int o = 8; o > 0; o >>= 1) {
            ps += __shfl_down_sync(0xffffffffu, ps, o, 16);
            pd += __shfl_down_sync(0xffffffffu, pd, o, 16);
        }
        if (tx == 0) {
            int gn = node0 + ty * 4 + i;
            if (gn < NN) { g_ssrc[gn] = ps; g_sdst[gn] = pd; }
        }
    }
}

// ============================================================
// K0 (side stream): zero deg + scan flags (int4 stores)
// ============================================================
__global__ __launch_bounds__(256) void k_zero() {
    int t = blockIdx.x * blockDim.x + threadIdx.x;
    if (t * 4 < NN)
        reinterpret_cast<int4*>(g_deg)[t] = make_int4(0, 0, 0, 0);
    if (t < NBLK) g_flagval[t] = 0;
}

// ============================================================
// K2: dst-degree histogram; the atomic's return value IS the
//     edge's rank within its dst segment -> store it coalesced.
// ============================================================
__global__ __launch_bounds__(256) void k_hist(const int* __restrict__ dst) {
    int t = blockIdx.x * blockDim.x + threadIdx.x;
    if (t * 4 >= NE) return;
    int4 d4 = reinterpret_cast<const int4*>(dst)[t];
    int4 r4;
    r4.x = atomicAdd(&g_deg[d4.x], 1);
    r4.y = atomicAdd(&g_deg[d4.y], 1);
    r4.z = atomicAdd(&g_deg[d4.z], 1);
    r4.w = atomicAdd(&g_deg[d4.w], 1);
    reinterpret_cast<int4*>(g_rank)[t] = r4;  // coalesced
}

// ============================================================
// K3: single-kernel exclusive scan with parallel lookback.
//     98 blocks (< 148 SMs, all co-resident). Each block publishes
//     its total+1 in one word; threads t<bid poll predecessors in
//     parallel and block-reduce the exclusive base.
// ============================================================
__global__ __launch_bounds__(256) void k_scan() {
    __shared__ int wsum[8];
    __shared__ int wred[8];
    __shared__ int s_base;
    const int bid  = blockIdx.x;
    const int lane = threadIdx.x & 31, wid = threadIdx.x >> 5;
    const int idx  = bid * SCAN_ELEMS + threadIdx.x * 4;

    int v[4];
    if (idx + 3 < NN) {
        int4 d = *reinterpret_cast<const int4*>(&g_deg[idx]);
        v[0] = d.x; v[1] = d.y; v[2] = d.z; v[3] = d.w;
    } else {
#pragma unroll
        for (int k = 0; k < 4; k++) v[k] = (idx + k < NN) ? g_deg[idx + k] : 0;
    }
    const int tot = v[0] + v[1] + v[2] + v[3];

    // warp inclusive scan of per-thread totals
    int x = tot;
#pragma unroll
    for (int o = 1; o < 32; o <<= 1) {
        int t = __shfl_up_sync(0xffffffffu, x, o);
        if (lane >= o) x += t;
    }
    if (lane == 31) wsum[wid] = x;
    __syncthreads();
    if (threadIdx.x < 32) {
        int w = (threadIdx.x < 8) ? wsum[threadIdx.x] : 0;
#pragma unroll
        for (int o = 1; o < 8; o <<= 1) {
            int t = __shfl_up_sync(0xffffffffu, w, o);
            if (threadIdx.x >= (unsigned)o) w += t;
        }
        if (threadIdx.x < 8) wsum[threadIdx.x] = w;   // inclusive warp prefixes
    }
    __syncthreads();

    // publish this block's total (value+1 doubles as the ready flag)
    if (threadIdx.x == 0)
        ((volatile int*)g_flagval)[bid] = wsum[7] + 1;

    // parallel lookback: thread t polls predecessor t
    int pre = 0;
    if ((int)threadIdx.x < bid) {
        volatile int* fv = g_flagval;
        int f;
        do { f = fv[threadIdx.x]; } while (f == 0);
        pre = f - 1;
    }
    // block reduce of pre
#pragma unroll
    for (int o = 16; o > 0; o >>= 1) pre += __shfl_down_sync(0xffffffffu, pre, o);
    if (lane == 0) wred[wid] = pre;
    __syncthreads();
    if (threadIdx.x < 32) {
        int r = (threadIdx.x < 8) ? wred[threadIdx.x] : 0;
#pragma unroll
        for (int o = 4; o > 0; o >>= 1) r += __shfl_down_sync(0xffffffffu, r, o);
        if (threadIdx.x == 0) s_base = r;
    }
    __syncthreads();

    int run = s_base + ((wid > 0) ? wsum[wid - 1] : 0) + (x - tot);
#pragma unroll
    for (int k = 0; k < 4; k++) {
        if (idx + k < NN) g_off[idx + k] = run;
        run += v[k];
    }
}

// ============================================================
// K4: CSR scatter — atomic-free. Slot = off[dst] + rank.
// ============================================================
__global__ __launch_bounds__(256) void k_scatter(const int* __restrict__ src,
                                                 const int* __restrict__ dst) {
    int t = blockIdx.x * blockDim.x + threadIdx.x;
    if (t * 4 >= NE) return;
    int4 s4 = reinterpret_cast<const int4*>(src)[t];
    int4 d4 = reinterpret_cast<const int4*>(dst)[t];
    int4 r4 = reinterpret_cast<const int4*>(g_rank)[t];
    int ss[4] = {s4.x, s4.y, s4.z, s4.w};
    int dd[4] = {d4.x, d4.y, d4.z, d4.w};
    int rr[4] = {r4.x, r4.y, r4.z, r4.w};

    int o[4];
#pragma unroll
    for (int k = 0; k < 4; k++) o[k] = __ldg(&g_off[dd[k]]);
#pragma unroll
    for (int k = 0; k < 4; k++) g_csrc[o[k] + rr[k]] = ss[k];
}

// ============================================================
// K5: per-dst gather-reduce. Edge score recomputed in place:
//     e = leaky(ssrc[s] + sdst[node]). Softmax without max shift
//     (scores O(1); shift cancels in ratio) + weighted sum + elu.
//     One warp per node; lane covers cols (lane, lane+32).
// ============================================================
__global__ __launch_bounds__(256) void k_aggr(float* __restrict__ out) {
    int node = blockIdx.x * 8 + (threadIdx.x >> 5);
    int lane = threadIdx.x & 31;
    if (node >= NN) return;

    int start = g_off[node];
    int dg    = g_deg[node];

    if (dg == 0) {
        out[(size_t)node * OUTD + lane] = 0.f;
        out[(size_t)node * OUTD + 32 + lane] = 0.f;
        return;
    }

    const float sd = g_sdst[node];

    float acc0 = 0.f, acc1 = 0.f, denom = 0.f;
    int j = 0;
    for (; j + 3 < dg; j += 4) {
        int e0 = start + j;
        int s0 = g_csrc[e0], s1 = g_csrc[e0 + 1], s2 = g_csrc[e0 + 2], s3 = g_csrc[e0 + 3];
        float v0 = __ldg(&g_ssrc[s0]) + sd;
        float v1 = __ldg(&g_ssrc[s1]) + sd;
        float v2 = __ldg(&g_ssrc[s2]) + sd;
        float v3 = __ldg(&g_ssrc[s3]) + sd;
        const float* zp0 = &g_z[(size_t)s0 * OUTD];
        const float* zp1 = &g_z[(size_t)s1 * OUTD];
        const float* zp2 = &g_z[(size_t)s2 * OUTD];
        const float* zp3 = &g_z[(size_t)s3 * OUTD];
        float a00 = zp0[lane], a01 = zp0[32 + lane];
        float a10 = zp1[lane], a11 = zp1[32 + lane];
        float a20 = zp2[lane], a21 = zp2[32 + lane];
        float a30 = zp3[lane], a31 = zp3[32 + lane];
        float x0 = __expf(v0 > 0.f ? v0 : 0.01f * v0);
        float x1 = __expf(v1 > 0.f ? v1 : 0.01f * v1);
        float x2 = __expf(v2 > 0.f ? v2 : 0.01f * v2);
        float x3 = __expf(v3 > 0.f ? v3 : 0.01f * v3);
        denom += (x0 + x1) + (x2 + x3);
        acc0 += x0 * a00 + x1 * a10 + x2 * a20 + x3 * a30;
        acc1 += x0 * a01 + x1 * a11 + x2 * a21 + x3 * a31;
    }
    for (; j < dg; j++) {
        int s = g_csrc[start + j];
        float v = __ldg(&g_ssrc[s]) + sd;
        float x = __expf(v > 0.f ? v : 0.01f * v);
        const float* zp = &g_z[(size_t)s * OUTD];
        denom += x;
        acc0 += x * zp[lane];
        acc1 += x * zp[32 + lane];
    }

    float inv = 1.0f / denom;     // denom > 0 (all terms > 0)
    float o0 = acc0 * inv;
    float o1 = acc1 * inv;
    out[(size_t)node * OUTD + lane]      = o0 > 0.f ? o0 : (__expf(o0) - 1.0f);
    out[(size_t)node * OUTD + 32 + lane] = o1 > 0.f ? o1 : (__expf(o1) - 1.0f);
}

// ============================================================
// Fork/join: gemm on the main (capture) stream; CSR build on a
// side stream; join before aggr. Streams/events are host-side
// objects created once — no device memory involved.
// ============================================================
extern "C" void kernel_launch(void* const* d_in, const int* in_sizes, int n_in,
                              void* d_out, int out_size) {
    const float* h   = (const float*)d_in[0];
    const int*   src = (const int*)d_in[1];
    const int*   dst = (const int*)d_in[2];
    const float* W   = (const float*)d_in[3];
    const float* a   = (const float*)d_in[4];
    float* out = (float*)d_out;

    static cudaStream_t s_side = nullptr;
    static cudaEvent_t  ev_fork = nullptr, ev_join = nullptr;
    if (s_side == nullptr) {
        cudaStreamCreateWithFlags(&s_side, cudaStreamNonBlocking);
        cudaEventCreateWithFlags(&ev_fork, cudaEventDisableTiming);
        cudaEventCreateWithFlags(&ev_join, cudaEventDisableTiming);
    }

    // fork side stream off the main (capture) stream
    cudaEventRecord(ev_fork, 0);
    cudaStreamWaitEvent(s_side, ev_fork, 0);

    // main stream: GEMM + fused scores (FFMA-bound)
    k_gemm<<<(NN + 63) / 64, 256>>>(h, W, a);

    // side stream: CSR build (memory/atomic-bound, independent of gemm)
    k_zero   <<<(NN / 4 + 255) / 256, 256, 0, s_side>>>();
    k_hist   <<<(NE / 4 + 255) / 256, 256, 0, s_side>>>(dst);
    k_scan   <<<NBLK, 256, 0, s_side>>>();
    k_scatter<<<(NE / 4 + 255) / 256, 256, 0, s_side>>>(src, dst);

    // join
    cudaEventRecord(ev_join, s_side);
    cudaStreamWaitEvent(0, ev_join, 0);

    k_aggr<<<(NN + 7) / 8, 256>>>(out);
}

// round 12
// speedup vs baseline: 1.6790x; 1.1239x over previous
#include <cuda_runtime.h>
#include <math_constants.h>

#define NN 100000
#define NE 1600000
#define IND 128
#define OUTD 64

#define SCAN_ELEMS 1024                       // per block (256 thr x 4)
#define NBLK ((NN + SCAN_ELEMS - 1) / SCAN_ELEMS)   // 98

// ---- scratch (static device globals; no allocation) ----
__device__ __align__(16) float g_z[(size_t)NN * OUTD];     // 25.6 MB
__device__ __align__(16) float g_ssrc[NN];
__device__ __align__(16) float g_sdst[NN];
__device__ __align__(16) int   g_deg[NN];
__device__ __align__(16) int   g_off[NN];
__device__ __align__(16) int   g_rank[NE];                 // 6.4 MB
__device__ __align__(16) int   g_csrc[NE];                 // 6.4 MB
__device__ int g_flagval[NBLK];                            // scan lookback: total+1, 0=unpublished

// ============================================================
// K1: z = h @ W^T  (128x64 tile, 8x4/thread) + fused score
//     epilogue (s_src = z@a[:64], s_dst = z@a[64:])
// ============================================================
__global__ __launch_bounds__(256) void k_gemm(const float* __restrict__ h,
                                              const float* __restrict__ W,
                                              const float* __restrict__ a) {
    __shared__ __align__(16) float hs[32][132];  // hs[k][node] (128 + pad)
    __shared__ __align__(16) float ws[32][68];   // ws[k][out] = W[out][k]

    const int tx = threadIdx.x & 15;        // out tile (x4)
    const int ty = threadIdx.x >> 4;        // node tile (x8)
    const int node0 = blockIdx.x * 128;

    float acc[8][4];
#pragma unroll
    for (int i = 0; i < 8; i++)
#pragma unroll
        for (int j = 0; j < 4; j++) acc[i][j] = 0.f;

    for (int k0 = 0; k0 < IND; k0 += 32) {
        // load h tile: 128 rows x 8 float4; 2 threads/row, 4 float4 each
        {
            const int r  = threadIdx.x >> 1;             // 0..127
            const int q0 = (threadIdx.x & 1) * 4;        // float4 index 0 or 4
            int gn = node0 + r;
            float4 v[4];
            if (gn < NN) {
                const float4* hp = reinterpret_cast<const float4*>(h + (size_t)gn * IND + k0) + q0;
#pragma unroll
                for (int q = 0; q < 4; q++) v[q] = hp[q];
            } else {
#pragma unroll
                for (int q = 0; q < 4; q++) v[q] = make_float4(0.f, 0.f, 0.f, 0.f);
            }
#pragma unroll
            for (int q = 0; q < 4; q++) {
                int kk = (q0 + q) * 4;
                hs[kk + 0][r] = v[q].x; hs[kk + 1][r] = v[q].y;
                hs[kk + 2][r] = v[q].z; hs[kk + 3][r] = v[q].w;
            }
        }
        // load W tile: 64 rows x 8 float4; 4 threads/row, 2 float4 each
        {
            const int r  = threadIdx.x >> 2;             // 0..63
            const int q0 = (threadIdx.x & 3) * 2;        // float4 index
            const float4* wp = reinterpret_cast<const float4*>(W + (size_t)r * IND + k0) + q0;
            float4 w0 = wp[0], w1 = wp[1];
            int kk = q0 * 4;
            ws[kk + 0][r] = w0.x; ws[kk + 1][r] = w0.y; ws[kk + 2][r] = w0.z; ws[kk + 3][r] = w0.w;
            ws[kk + 4][r] = w1.x; ws[kk + 5][r] = w1.y; ws[kk + 6][r] = w1.z; ws[kk + 7][r] = w1.w;
        }
        __syncthreads();
#pragma unroll
        for (int kk = 0; kk < 32; kk++) {
            float4 a0 = *reinterpret_cast<const float4*>(&hs[kk][ty * 8]);
            float4 a1 = *reinterpret_cast<const float4*>(&hs[kk][ty * 8 + 4]);
            float4 bv = *reinterpret_cast<const float4*>(&ws[kk][tx * 4]);
            float aa[8] = {a0.x, a0.y, a0.z, a0.w, a1.x, a1.y, a1.z, a1.w};
            float bb[4] = {bv.x, bv.y, bv.z, bv.w};
#pragma unroll
            for (int i = 0; i < 8; i++)
#pragma unroll
                for (int j = 0; j < 4; j++) acc[i][j] += aa[i] * bb[j];
        }
        __syncthreads();
    }

    // store z tile
#pragma unroll
    for (int i = 0; i < 8; i++) {
        int gn = node0 + ty * 8 + i;
        if (gn < NN) {
            float4 v = make_float4(acc[i][0], acc[i][1], acc[i][2], acc[i][3]);
            *reinterpret_cast<float4*>(&g_z[(size_t)gn * OUTD + tx * 4]) = v;
        }
    }

    // fused score epilogue: reduce across the 16 tx threads (width-16 shuffle)
    float as[4], ad[4];
#pragma unroll
    for (int j = 0; j < 4; j++) {
        as[j] = __ldg(&a[tx * 4 + j]);
        ad[j] = __ldg(&a[64 + tx * 4 + j]);
    }
#pragma unroll
    for (int i = 0; i < 8; i++) {
        float ps = acc[i][0] * as[0] + acc[i][1] * as[1] + acc[i][2] * as[2] + acc[i][3] * as[3];
        float pd = acc[i][0] * ad[0] + acc[i][1] * ad[1] + acc[i][2] * ad[2] + acc[i][3] * ad[3];
#pragma unroll
        for (int o = 8; o > 0; o >>= 1) {
            ps += __shfl_down_sync(0xffffffffu, ps, o, 16);
            pd += __shfl_down_sync(0xffffffffu, pd, o, 16);
        }
        if (tx == 0) {
            int gn = node0 + ty * 8 + i;
            if (gn < NN) { g_ssrc[gn] = ps; g_sdst[gn] = pd; }
        }
    }
}

// ============================================================
// K0 (side stream): zero deg + scan flags (int4 stores)
// ============================================================
__global__ __launch_bounds__(256) void k_zero() {
    int t = blockIdx.x * blockDim.x + threadIdx.x;
    if (t * 4 < NN)
        reinterpret_cast<int4*>(g_deg)[t] = make_int4(0, 0, 0, 0);
    if (t < NBLK) g_flagval[t] = 0;
}

// ============================================================
// K2: dst-degree histogram; atomic return value = rank
// ============================================================
__global__ __launch_bounds__(256) void k_hist(const int* __restrict__ dst) {
    int t = blockIdx.x * blockDim.x + threadIdx.x;
    if (t * 4 >= NE) return;
    int4 d4 = reinterpret_cast<const int4*>(dst)[t];
    int4 r4;
    r4.x = atomicAdd(&g_deg[d4.x], 1);
    r4.y = atomicAdd(&g_deg[d4.y], 1);
    r4.z = atomicAdd(&g_deg[d4.z], 1);
    r4.w = atomicAdd(&g_deg[d4.w], 1);
    reinterpret_cast<int4*>(g_rank)[t] = r4;  // coalesced
}

// ============================================================
// K3: single-kernel exclusive scan with parallel lookback.
// ============================================================
__global__ __launch_bounds__(256) void k_scan() {
    __shared__ int wsum[8];
    __shared__ int wred[8];
    __shared__ int s_base;
    const int bid  = blockIdx.x;
    const int lane = threadIdx.x & 31, wid = threadIdx.x >> 5;
    const int idx  = bid * SCAN_ELEMS + threadIdx.x * 4;

    int v[4];
    if (idx + 3 < NN) {
        int4 d = *reinterpret_cast<const int4*>(&g_deg[idx]);
        v[0] = d.x; v[1] = d.y; v[2] = d.z; v[3] = d.w;
    } else {
#pragma unroll
        for (int k = 0; k < 4; k++) v[k] = (idx + k < NN) ? g_deg[idx + k] : 0;
    }
    const int tot = v[0] + v[1] + v[2] + v[3];

    int x = tot;
#pragma unroll
    for (int o = 1; o < 32; o <<= 1) {
        int t = __shfl_up_sync(0xffffffffu, x, o);
        if (lane >= o) x += t;
    }
    if (lane == 31) wsum[wid] = x;
    __syncthreads();
    if (threadIdx.x < 32) {
        int w = (threadIdx.x < 8) ? wsum[threadIdx.x] : 0;
#pragma unroll
        for (int o = 1; o < 8; o <<= 1) {
            int t = __shfl_up_sync(0xffffffffu, w, o);
            if (threadIdx.x >= (unsigned)o) w += t;
        }
        if (threadIdx.x < 8) wsum[threadIdx.x] = w;
    }
    __syncthreads();

    if (threadIdx.x == 0)
        ((volatile int*)g_flagval)[bid] = wsum[7] + 1;

    int pre = 0;
    if ((int)threadIdx.x < bid) {
        volatile int* fv = g_flagval;
        int f;
        do { f = fv[threadIdx.x]; } while (f == 0);
        pre = f - 1;
    }
#pragma unroll
    for (int o = 16; o > 0; o >>= 1) pre += __shfl_down_sync(0xffffffffu, pre, o);
    if (lane == 0) wred[wid] = pre;
    __syncthreads();
    if (threadIdx.x < 32) {
        int r = (threadIdx.x < 8) ? wred[threadIdx.x] : 0;
#pragma unroll
        for (int o = 4; o > 0; o >>= 1) r += __shfl_down_sync(0xffffffffu, r, o);
        if (threadIdx.x == 0) s_base = r;
    }
    __syncthreads();

    int run = s_base + ((wid > 0) ? wsum[wid - 1] : 0) + (x - tot);
#pragma unroll
    for (int k = 0; k < 4; k++) {
        if (idx + k < NN) g_off[idx + k] = run;
        run += v[k];
    }
}

// ============================================================
// K4: CSR scatter — atomic-free. Slot = off[dst] + rank.
// ============================================================
__global__ __launch_bounds__(256) void k_scatter(const int* __restrict__ src,
                                                 const int* __restrict__ dst) {
    int t = blockIdx.x * blockDim.x + threadIdx.x;
    if (t * 4 >= NE) return;
    int4 s4 = reinterpret_cast<const int4*>(src)[t];
    int4 d4 = reinterpret_cast<const int4*>(dst)[t];
    int4 r4 = reinterpret_cast<const int4*>(g_rank)[t];
    int ss[4] = {s4.x, s4.y, s4.z, s4.w};
    int dd[4] = {d4.x, d4.y, d4.z, d4.w};
    int rr[4] = {r4.x, r4.y, r4.z, r4.w};

    int o[4];
#pragma unroll
    for (int k = 0; k < 4; k++) o[k] = __ldg(&g_off[dd[k]]);
#pragma unroll
    for (int k = 0; k < 4; k++) g_csrc[o[k] + rr[k]] = ss[k];
}

// ============================================================
// K5: per-dst gather-reduce; 8x unrolled for MLP.
//     e = leaky(ssrc[s] + sdst[node]); softmax without max shift
//     (scores O(1); shift cancels in ratio) + weighted sum + elu.
// ============================================================
__global__ __launch_bounds__(256) void k_aggr(float* __restrict__ out) {
    int node = blockIdx.x * 8 + (threadIdx.x >> 5);
    int lane = threadIdx.x & 31;
    if (node >= NN) return;

    int start = g_off[node];
    int dg    = g_deg[node];

    if (dg == 0) {
        out[(size_t)node * OUTD + lane] = 0.f;
        out[(size_t)node * OUTD + 32 + lane] = 0.f;
        return;
    }

    const float sd = g_sdst[node];

    float acc0 = 0.f, acc1 = 0.f, denom = 0.f;
    int j = 0;
    for (; j + 7 < dg; j += 8) {
        int e0 = start + j;
        int s[8];
#pragma unroll
        for (int k = 0; k < 8; k++) s[k] = g_csrc[e0 + k];
        float v[8];
#pragma unroll
        for (int k = 0; k < 8; k++) v[k] = __ldg(&g_ssrc[s[k]]) + sd;
        float z0[8], z1[8];
#pragma unroll
        for (int k = 0; k < 8; k++) {
            const float* zp = &g_z[(size_t)s[k] * OUTD];
            z0[k] = zp[lane];
            z1[k] = zp[32 + lane];
        }
#pragma unroll
        for (int k = 0; k < 8; k++) {
            float xv = __expf(v[k] > 0.f ? v[k] : 0.01f * v[k]);
            denom += xv;
            acc0 += xv * z0[k];
            acc1 += xv * z1[k];
        }
    }
    for (; j < dg; j++) {
        int s = g_csrc[start + j];
        float v = __ldg(&g_ssrc[s]) + sd;
        float x = __expf(v > 0.f ? v : 0.01f * v);
        const float* zp = &g_z[(size_t)s * OUTD];
        denom += x;
        acc0 += x * zp[lane];
        acc1 += x * zp[32 + lane];
    }

    float inv = 1.0f / denom;     // denom > 0 (all terms > 0)
    float o0 = acc0 * inv;
    float o1 = acc1 * inv;
    out[(size_t)node * OUTD + lane]      = o0 > 0.f ? o0 : (__expf(o0) - 1.0f);
    out[(size_t)node * OUTD + 32 + lane] = o1 > 0.f ? o1 : (__expf(o1) - 1.0f);
}

// ============================================================
// Fork/join: gemm on the main (capture) stream; CSR build on a
// side stream; join before aggr.
// ============================================================
extern "C" void kernel_launch(void* const* d_in, const int* in_sizes, int n_in,
                              void* d_out, int out_size) {
    const float* h   = (const float*)d_in[0];
    const int*   src = (const int*)d_in[1];
    const int*   dst = (const int*)d_in[2];
    const float* W   = (const float*)d_in[3];
    const float* a   = (const float*)d_in[4];
    float* out = (float*)d_out;

    static cudaStream_t s_side = nullptr;
    static cudaEvent_t  ev_fork = nullptr, ev_join = nullptr;
    if (s_side == nullptr) {
        cudaStreamCreateWithFlags(&s_side, cudaStreamNonBlocking);
        cudaEventCreateWithFlags(&ev_fork, cudaEventDisableTiming);
        cudaEventCreateWithFlags(&ev_join, cudaEventDisableTiming);
    }

    // fork side stream off the main (capture) stream
    cudaEventRecord(ev_fork, 0);
    cudaStreamWaitEvent(s_side, ev_fork, 0);

    // main stream: GEMM + fused scores (FFMA-bound)
    k_gemm<<<(NN + 127) / 128, 256>>>(h, W, a);

    // side stream: CSR build (memory/atomic-bound, independent of gemm)
    k_zero   <<<(NN / 4 + 255) / 256, 256, 0, s_side>>>();
    k_hist   <<<(NE / 4 + 255) / 256, 256, 0, s_side>>>(dst);
    k_scan   <<<NBLK, 256, 0, s_side>>>();
    k_scatter<<<(NE / 4 + 255) / 256, 256, 0, s_side>>>(src, dst);

    // join
    cudaEventRecord(ev_join, s_side);
    cudaStreamWaitEvent(0, ev_join, 0);

    k_aggr<<<(NN + 7) / 8, 256>>>(out);
}

// round 13
// speedup vs baseline: 1.7934x; 1.0682x over previous
#include <cuda_runtime.h>
#include <math_constants.h>

#define NN 100000
#define NE 1600000
#define IND 128
#define OUTD 64

#define SCAN_ELEMS 1024                       // per block (256 thr x 4)
#define NBLK ((NN + SCAN_ELEMS - 1) / SCAN_ELEMS)   // 98

// ---- scratch (static device globals; no allocation) ----
__device__ __align__(16) float g_z[(size_t)NN * OUTD];     // 25.6 MB
__device__ __align__(16) float g_ssrc[NN];
__device__ __align__(16) float g_sdst[NN];
__device__ __align__(16) int   g_deg[NN];
__device__ __align__(16) int   g_off[NN];
__device__ __align__(16) int   g_rank[NE];                 // 6.4 MB
__device__ __align__(16) int   g_csrc[NE];                 // 6.4 MB
__device__ int g_flagval[NBLK];                            // scan lookback: total+1, 0=unpublished

// ============================================================
// K1: z = h @ W^T  (128x64 tile, 8x4/thread) + fused score
//     epilogue (s_src = z@a[:64], s_dst = z@a[64:])
// ============================================================
__global__ __launch_bounds__(256) void k_gemm(const float* __restrict__ h,
                                              const float* __restrict__ W,
                                              const float* __restrict__ a) {
    __shared__ __align__(16) float hs[32][132];  // hs[k][node] (128 + pad)
    __shared__ __align__(16) float ws[32][68];   // ws[k][out] = W[out][k]

    const int tx = threadIdx.x & 15;        // out tile (x4)
    const int ty = threadIdx.x >> 4;        // node tile (x8)
    const int node0 = blockIdx.x * 128;

    float acc[8][4];
#pragma unroll
    for (int i = 0; i < 8; i++)
#pragma unroll
        for (int j = 0; j < 4; j++) acc[i][j] = 0.f;

    for (int k0 = 0; k0 < IND; k0 += 32) {
        // load h tile: 128 rows x 8 float4; 2 threads/row, 4 float4 each
        {
            const int r  = threadIdx.x >> 1;             // 0..127
            const int q0 = (threadIdx.x & 1) * 4;        // float4 index 0 or 4
            int gn = node0 + r;
            float4 v[4];
            if (gn < NN) {
                const float4* hp = reinterpret_cast<const float4*>(h + (size_t)gn * IND + k0) + q0;
#pragma unroll
                for (int q = 0; q < 4; q++) v[q] = hp[q];
            } else {
#pragma unroll
                for (int q = 0; q < 4; q++) v[q] = make_float4(0.f, 0.f, 0.f, 0.f);
            }
#pragma unroll
            for (int q = 0; q < 4; q++) {
                int kk = (q0 + q) * 4;
                hs[kk + 0][r] = v[q].x; hs[kk + 1][r] = v[q].y;
                hs[kk + 2][r] = v[q].z; hs[kk + 3][r] = v[q].w;
            }
        }
        // load W tile: 64 rows x 8 float4; 4 threads/row, 2 float4 each
        {
            const int r  = threadIdx.x >> 2;             // 0..63
            const int q0 = (threadIdx.x & 3) * 2;        // float4 index
            const float4* wp = reinterpret_cast<const float4*>(W + (size_t)r * IND + k0) + q0;
            float4 w0 = wp[0], w1 = wp[1];
            int kk = q0 * 4;
            ws[kk + 0][r] = w0.x; ws[kk + 1][r] = w0.y; ws[kk + 2][r] = w0.z; ws[kk + 3][r] = w0.w;
            ws[kk + 4][r] = w1.x; ws[kk + 5][r] = w1.y; ws[kk + 6][r] = w1.z; ws[kk + 7][r] = w1.w;
        }
        __syncthreads();
#pragma unroll
        for (int kk = 0; kk < 32; kk++) {
            float4 a0 = *reinterpret_cast<const float4*>(&hs[kk][ty * 8]);
            float4 a1 = *reinterpret_cast<const float4*>(&hs[kk][ty * 8 + 4]);
            float4 bv = *reinterpret_cast<const float4*>(&ws[kk][tx * 4]);
            float aa[8] = {a0.x, a0.y, a0.z, a0.w, a1.x, a1.y, a1.z, a1.w};
            float bb[4] = {bv.x, bv.y, bv.z, bv.w};
#pragma unroll
            for (int i = 0; i < 8; i++)
#pragma unroll
                for (int j = 0; j < 4; j++) acc[i][j] += aa[i] * bb[j];
        }
        __syncthreads();
    }

    // store z tile
#pragma unroll
    for (int i = 0; i < 8; i++) {
        int gn = node0 + ty * 8 + i;
        if (gn < NN) {
            float4 v = make_float4(acc[i][0], acc[i][1], acc[i][2], acc[i][3]);
            *reinterpret_cast<float4*>(&g_z[(size_t)gn * OUTD + tx * 4]) = v;
        }
    }

    // fused score epilogue: reduce across the 16 tx threads (width-16 shuffle)
    float as[4], ad[4];
#pragma unroll
    for (int j = 0; j < 4; j++) {
        as[j] = __ldg(&a[tx * 4 + j]);
        ad[j] = __ldg(&a[64 + tx * 4 + j]);
    }
#pragma unroll
    for (int i = 0; i < 8; i++) {
        float ps = acc[i][0] * as[0] + acc[i][1] * as[1] + acc[i][2] * as[2] + acc[i][3] * as[3];
        float pd = acc[i][0] * ad[0] + acc[i][1] * ad[1] + acc[i][2] * ad[2] + acc[i][3] * ad[3];
#pragma unroll
        for (int o = 8; o > 0; o >>= 1) {
            ps += __shfl_down_sync(0xffffffffu, ps, o, 16);
            pd += __shfl_down_sync(0xffffffffu, pd, o, 16);
        }
        if (tx == 0) {
            int gn = node0 + ty * 8 + i;
            if (gn < NN) { g_ssrc[gn] = ps; g_sdst[gn] = pd; }
        }
    }
}

// ============================================================
// K0 (side stream): zero deg + scan flags (int4 stores)
// ============================================================
__global__ __launch_bounds__(256) void k_zero() {
    int t = blockIdx.x * blockDim.x + threadIdx.x;
    if (t * 4 < NN)
        reinterpret_cast<int4*>(g_deg)[t] = make_int4(0, 0, 0, 0);
    if (t < NBLK) g_flagval[t] = 0;
}

// ============================================================
// K2: dst-degree histogram; atomic return value = rank
// ============================================================
__global__ __launch_bounds__(256) void k_hist(const int* __restrict__ dst) {
    int t = blockIdx.x * blockDim.x + threadIdx.x;
    if (t * 4 >= NE) return;
    int4 d4 = reinterpret_cast<const int4*>(dst)[t];
    int4 r4;
    r4.x = atomicAdd(&g_deg[d4.x], 1);
    r4.y = atomicAdd(&g_deg[d4.y], 1);
    r4.z = atomicAdd(&g_deg[d4.z], 1);
    r4.w = atomicAdd(&g_deg[d4.w], 1);
    reinterpret_cast<int4*>(g_rank)[t] = r4;  // coalesced
}

// ============================================================
// K3: single-kernel exclusive scan with parallel lookback.
// ============================================================
__global__ __launch_bounds__(256) void k_scan() {
    __shared__ int wsum[8];
    __shared__ int wred[8];
    __shared__ int s_base;
    const int bid  = blockIdx.x;
    const int lane = threadIdx.x & 31, wid = threadIdx.x >> 5;
    const int idx  = bid * SCAN_ELEMS + threadIdx.x * 4;

    int v[4];
    if (idx + 3 < NN) {
        int4 d = *reinterpret_cast<const int4*>(&g_deg[idx]);
        v[0] = d.x; v[1] = d.y; v[2] = d.z; v[3] = d.w;
    } else {
#pragma unroll
        for (int k = 0; k < 4; k++) v[k] = (idx + k < NN) ? g_deg[idx + k] : 0;
    }
    const int tot = v[0] + v[1] + v[2] + v[3];

    int x = tot;
#pragma unroll
    for (int o = 1; o < 32; o <<= 1) {
        int t = __shfl_up_sync(0xffffffffu, x, o);
        if (lane >= o) x += t;
    }
    if (lane == 31) wsum[wid] = x;
    __syncthreads();
    if (threadIdx.x < 32) {
        int w = (threadIdx.x < 8) ? wsum[threadIdx.x] : 0;
#pragma unroll
        for (int o = 1; o < 8; o <<= 1) {
            int t = __shfl_up_sync(0xffffffffu, w, o);
            if (threadIdx.x >= (unsigned)o) w += t;
        }
        if (threadIdx.x < 8) wsum[threadIdx.x] = w;
    }
    __syncthreads();

    if (threadIdx.x == 0)
        ((volatile int*)g_flagval)[bid] = wsum[7] + 1;

    int pre = 0;
    if ((int)threadIdx.x < bid) {
        volatile int* fv = g_flagval;
        int f;
        do { f = fv[threadIdx.x]; } while (f == 0);
        pre = f - 1;
    }
#pragma unroll
    for (int o = 16; o > 0; o >>= 1) pre += __shfl_down_sync(0xffffffffu, pre, o);
    if (lane == 0) wred[wid] = pre;
    __syncthreads();
    if (threadIdx.x < 32) {
        int r = (threadIdx.x < 8) ? wred[threadIdx.x] : 0;
#pragma unroll
        for (int o = 4; o > 0; o >>= 1) r += __shfl_down_sync(0xffffffffu, r, o);
        if (threadIdx.x == 0) s_base = r;
    }
    __syncthreads();

    int run = s_base + ((wid > 0) ? wsum[wid - 1] : 0) + (x - tot);
#pragma unroll
    for (int k = 0; k < 4; k++) {
        if (idx + k < NN) g_off[idx + k] = run;
        run += v[k];
    }
}

// ============================================================
// K4: CSR scatter — atomic-free. Slot = off[dst] + rank.
// ============================================================
__global__ __launch_bounds__(256) void k_scatter(const int* __restrict__ src,
                                                 const int* __restrict__ dst) {
    int t = blockIdx.x * blockDim.x + threadIdx.x;
    if (t * 4 >= NE) return;
    int4 s4 = reinterpret_cast<const int4*>(src)[t];
    int4 d4 = reinterpret_cast<const int4*>(dst)[t];
    int4 r4 = reinterpret_cast<const int4*>(g_rank)[t];
    int ss[4] = {s4.x, s4.y, s4.z, s4.w};
    int dd[4] = {d4.x, d4.y, d4.z, d4.w};
    int rr[4] = {r4.x, r4.y, r4.z, r4.w};

    int o[4];
#pragma unroll
    for (int k = 0; k < 4; k++) o[k] = __ldg(&g_off[dd[k]]);
#pragma unroll
    for (int k = 0; k < 4; k++) g_csrc[o[k] + rr[k]] = ss[k];
}

// ============================================================
// K5: per-dst gather-reduce, half-warp/float4 edition.
//     Each 16-lane half-warp loads a full 256B z-row with 16
//     LDG.128 (4x fewer load instrs than scalar); the two halves
//     process different edges (8 edges in flight per warp iter).
//     Halves combine via shfl_xor(16); float4 coalesced output.
//     e = leaky(ssrc[s] + sdst[node]); softmax without max shift
//     (scores O(1); shift cancels in ratio) + weighted sum + elu.
// ============================================================
__global__ __launch_bounds__(256) void k_aggr(float* __restrict__ out) {
    int node = blockIdx.x * 8 + (threadIdx.x >> 5);
    int lane = threadIdx.x & 31;
    int half = lane >> 4;        // 0 or 1: which edge subset
    int hl   = lane & 15;        // float4 index within row (cols 4*hl..4*hl+3)
    if (node >= NN) return;

    float4* orow = reinterpret_cast<float4*>(out + (size_t)node * OUTD);

    int start = g_off[node];
    int dg    = g_deg[node];
    if (dg == 0) {
        if (half == 0) orow[hl] = make_float4(0.f, 0.f, 0.f, 0.f);
        return;
    }
    const float sd = g_sdst[node];

    float4 acc = make_float4(0.f, 0.f, 0.f, 0.f);
    float denom = 0.f;

    int j = 0;
    for (; j + 7 < dg; j += 8) {
        int e0 = start + j + half * 4;
        int s[4];
#pragma unroll
        for (int k = 0; k < 4; k++) s[k] = g_csrc[e0 + k];
        float v[4];
#pragma unroll
        for (int k = 0; k < 4; k++) v[k] = __ldg(&g_ssrc[s[k]]) + sd;
        float4 z[4];
#pragma unroll
        for (int k = 0; k < 4; k++)
            z[k] = __ldg(&reinterpret_cast<const float4*>(&g_z[(size_t)s[k] * OUTD])[hl]);
#pragma unroll
        for (int k = 0; k < 4; k++) {
            float x = __expf(v[k] > 0.f ? v[k] : 0.01f * v[k]);
            denom += x;
            acc.x += x * z[k].x; acc.y += x * z[k].y;
            acc.z += x * z[k].z; acc.w += x * z[k].w;
        }
    }
    // pairs: one edge per half
    for (; j + 1 < dg; j += 2) {
        int s = g_csrc[start + j + half];
        float v = __ldg(&g_ssrc[s]) + sd;
        float x = __expf(v > 0.f ? v : 0.01f * v);
        float4 z = __ldg(&reinterpret_cast<const float4*>(&g_z[(size_t)s * OUTD])[hl]);
        denom += x;
        acc.x += x * z.x; acc.y += x * z.y; acc.z += x * z.z; acc.w += x * z.w;
    }
    // last odd edge: half 0 only
    if (j < dg && half == 0) {
        int s = g_csrc[start + j];
        float v = __ldg(&g_ssrc[s]) + sd;
        float x = __expf(v > 0.f ? v : 0.01f * v);
        float4 z = __ldg(&reinterpret_cast<const float4*>(&g_z[(size_t)s * OUTD])[hl]);
        denom += x;
        acc.x += x * z.x; acc.y += x * z.y; acc.z += x * z.z; acc.w += x * z.w;
    }

    // combine halves: lanes l and l^16 hold the same columns
    acc.x += __shfl_xor_sync(0xffffffffu, acc.x, 16);
    acc.y += __shfl_xor_sync(0xffffffffu, acc.y, 16);
    acc.z += __shfl_xor_sync(0xffffffffu, acc.z, 16);
    acc.w += __shfl_xor_sync(0xffffffffu, acc.w, 16);
    denom += __shfl_xor_sync(0xffffffffu, denom, 16);

    float inv = 1.0f / denom;     // denom > 0 (all terms > 0)
    float o0 = acc.x * inv, o1 = acc.y * inv, o2 = acc.z * inv, o3 = acc.w * inv;
    if (half == 0) {
        orow[hl] = make_float4(o0 > 0.f ? o0 : (__expf(o0) - 1.f),
                               o1 > 0.f ? o1 : (__expf(o1) - 1.f),
                               o2 > 0.f ? o2 : (__expf(o2) - 1.f),
                               o3 > 0.f ? o3 : (__expf(o3) - 1.f));
    }
}

// ============================================================
// Fork/join: gemm on the main (capture) stream; CSR build on a
// side stream; join before aggr.
// ============================================================
extern "C" void kernel_launch(void* const* d_in, const int* in_sizes, int n_in,
                              void* d_out, int out_size) {
    const float* h   = (const float*)d_in[0];
    const int*   src = (const int*)d_in[1];
    const int*   dst = (const int*)d_in[2];
    const float* W   = (const float*)d_in[3];
    const float* a   = (const float*)d_in[4];
    float* out = (float*)d_out;

    static cudaStream_t s_side = nullptr;
    static cudaEvent_t  ev_fork = nullptr, ev_join = nullptr;
    if (s_side == nullptr) {
        cudaStreamCreateWithFlags(&s_side, cudaStreamNonBlocking);
        cudaEventCreateWithFlags(&ev_fork, cudaEventDisableTiming);
        cudaEventCreateWithFlags(&ev_join, cudaEventDisableTiming);
    }

    // fork side stream off the main (capture) stream
    cudaEventRecord(ev_fork, 0);
    cudaStreamWaitEvent(s_side, ev_fork, 0);

    // main stream: GEMM + fused scores (FFMA-bound)
    k_gemm<<<(NN + 127) / 128, 256>>>(h, W, a);

    // side stream: CSR build (memory/atomic-bound, independent of gemm)
    k_zero   <<<(NN / 4 + 255) / 256, 256, 0, s_side>>>();
    k_hist   <<<(NE / 4 + 255) / 256, 256, 0, s_side>>>(dst);
    k_scan   <<<NBLK, 256, 0, s_side>>>();
    k_scatter<<<(NE / 4 + 255) / 256, 256, 0, s_side>>>(src, dst);

    // join
    cudaEventRecord(ev_join, s_side);
    cudaStreamWaitEvent(0, ev_join, 0);

    k_aggr<<<(NN + 7) / 8, 256>>>(out);
}

// round 14
// speedup vs baseline: 1.8029x; 1.0053x over previous
#include <cuda_runtime.h>
#include <math_constants.h>

#define NN 100000
#define NE 1600000
#define IND 128
#define OUTD 64

#define SCAN_ELEMS 1024                       // per block (256 thr x 4)
#define NBLK ((NN + SCAN_ELEMS - 1) / SCAN_ELEMS)   // 98

// ---- scratch (static device globals; no allocation) ----
__device__ __align__(16) float g_z[(size_t)NN * OUTD];     // 25.6 MB
__device__ __align__(16) float g_ssrc[NN];
__device__ __align__(16) float g_sdst[NN];
__device__ __align__(16) int   g_deg[NN];
__device__ __align__(16) int   g_off[NN];
__device__ __align__(16) int   g_rank[NE];                 // 6.4 MB
__device__ __align__(16) int   g_csrc[NE];                 // 6.4 MB
__device__ int g_flagval[NBLK];                            // scan lookback: total+1, 0=unpublished

// ============================================================
// K1: z = h @ W^T  (128x64 tile, 8x4/thread) + fused score
//     epilogue (s_src = z@a[:64], s_dst = z@a[64:])
// ============================================================
__global__ __launch_bounds__(256) void k_gemm(const float* __restrict__ h,
                                              const float* __restrict__ W,
                                              const float* __restrict__ a) {
    __shared__ __align__(16) float hs[32][132];  // hs[k][node] (128 + pad)
    __shared__ __align__(16) float ws[32][68];   // ws[k][out] = W[out][k]

    const int tx = threadIdx.x & 15;        // out tile (x4)
    const int ty = threadIdx.x >> 4;        // node tile (x8)
    const int node0 = blockIdx.x * 128;

    float acc[8][4];
#pragma unroll
    for (int i = 0; i < 8; i++)
#pragma unroll
        for (int j = 0; j < 4; j++) acc[i][j] = 0.f;

    for (int k0 = 0; k0 < IND; k0 += 32) {
        // load h tile: 128 rows x 8 float4; 2 threads/row, 4 float4 each
        {
            const int r  = threadIdx.x >> 1;             // 0..127
            const int q0 = (threadIdx.x & 1) * 4;        // float4 index 0 or 4
            int gn = node0 + r;
            float4 v[4];
            if (gn < NN) {
                const float4* hp = reinterpret_cast<const float4*>(h + (size_t)gn * IND + k0) + q0;
#pragma unroll
                for (int q = 0; q < 4; q++) v[q] = hp[q];
            } else {
#pragma unroll
                for (int q = 0; q < 4; q++) v[q] = make_float4(0.f, 0.f, 0.f, 0.f);
            }
#pragma unroll
            for (int q = 0; q < 4; q++) {
                int kk = (q0 + q) * 4;
                hs[kk + 0][r] = v[q].x; hs[kk + 1][r] = v[q].y;
                hs[kk + 2][r] = v[q].z; hs[kk + 3][r] = v[q].w;
            }
        }
        // load W tile: 64 rows x 8 float4; 4 threads/row, 2 float4 each
        {
            const int r  = threadIdx.x >> 2;             // 0..63
            const int q0 = (threadIdx.x & 3) * 2;        // float4 index
            const float4* wp = reinterpret_cast<const float4*>(W + (size_t)r * IND + k0) + q0;
            float4 w0 = wp[0], w1 = wp[1];
            int kk = q0 * 4;
            ws[kk + 0][r] = w0.x; ws[kk + 1][r] = w0.y; ws[kk + 2][r] = w0.z; ws[kk + 3][r] = w0.w;
            ws[kk + 4][r] = w1.x; ws[kk + 5][r] = w1.y; ws[kk + 6][r] = w1.z; ws[kk + 7][r] = w1.w;
        }
        __syncthreads();
#pragma unroll
        for (int kk = 0; kk < 32; kk++) {
            float4 a0 = *reinterpret_cast<const float4*>(&hs[kk][ty * 8]);
            float4 a1 = *reinterpret_cast<const float4*>(&hs[kk][ty * 8 + 4]);
            float4 bv = *reinterpret_cast<const float4*>(&ws[kk][tx * 4]);
            float aa[8] = {a0.x, a0.y, a0.z, a0.w, a1.x, a1.y, a1.z, a1.w};
            float bb[4] = {bv.x, bv.y, bv.z, bv.w};
#pragma unroll
            for (int i = 0; i < 8; i++)
#pragma unroll
                for (int j = 0; j < 4; j++) acc[i][j] += aa[i] * bb[j];
        }
        __syncthreads();
    }

    // store z tile
#pragma unroll
    for (int i = 0; i < 8; i++) {
        int gn = node0 + ty * 8 + i;
        if (gn < NN) {
            float4 v = make_float4(acc[i][0], acc[i][1], acc[i][2], acc[i][3]);
            *reinterpret_cast<float4*>(&g_z[(size_t)gn * OUTD + tx * 4]) = v;
        }
    }

    // fused score epilogue: reduce across the 16 tx threads (width-16 shuffle)
    float as[4], ad[4];
#pragma unroll
    for (int j = 0; j < 4; j++) {
        as[j] = __ldg(&a[tx * 4 + j]);
        ad[j] = __ldg(&a[64 + tx * 4 + j]);
    }
#pragma unroll
    for (int i = 0; i < 8; i++) {
        float ps = acc[i][0] * as[0] + acc[i][1] * as[1] + acc[i][2] * as[2] + acc[i][3] * as[3];
        float pd = acc[i][0] * ad[0] + acc[i][1] * ad[1] + acc[i][2] * ad[2] + acc[i][3] * ad[3];
#pragma unroll
        for (int o = 8; o > 0; o >>= 1) {
            ps += __shfl_down_sync(0xffffffffu, ps, o, 16);
            pd += __shfl_down_sync(0xffffffffu, pd, o, 16);
        }
        if (tx == 0) {
            int gn = node0 + ty * 8 + i;
            if (gn < NN) { g_ssrc[gn] = ps; g_sdst[gn] = pd; }
        }
    }
}

// ============================================================
// K0 (side stream): zero deg + scan flags (int4 stores)
// ============================================================
__global__ __launch_bounds__(256) void k_zero() {
    int t = blockIdx.x * blockDim.x + threadIdx.x;
    if (t * 4 < NN)
        reinterpret_cast<int4*>(g_deg)[t] = make_int4(0, 0, 0, 0);
    if (t < NBLK) g_flagval[t] = 0;
}

// ============================================================
// K2: dst-degree histogram; atomic return value = rank
// ============================================================
__global__ __launch_bounds__(256) void k_hist(const int* __restrict__ dst) {
    int t = blockIdx.x * blockDim.x + threadIdx.x;
    if (t * 4 >= NE) return;
    int4 d4 = reinterpret_cast<const int4*>(dst)[t];
    int4 r4;
    r4.x = atomicAdd(&g_deg[d4.x], 1);
    r4.y = atomicAdd(&g_deg[d4.y], 1);
    r4.z = atomicAdd(&g_deg[d4.z], 1);
    r4.w = atomicAdd(&g_deg[d4.w], 1);
    reinterpret_cast<int4*>(g_rank)[t] = r4;  // coalesced
}

// ============================================================
// K3: single-kernel exclusive scan with parallel lookback.
// ============================================================
__global__ __launch_bounds__(256) void k_scan() {
    __shared__ int wsum[8];
    __shared__ int wred[8];
    __shared__ int s_base;
    const int bid  = blockIdx.x;
    const int lane = threadIdx.x & 31, wid = threadIdx.x >> 5;
    const int idx  = bid * SCAN_ELEMS + threadIdx.x * 4;

    int v[4];
    if (idx + 3 < NN) {
        int4 d = *reinterpret_cast<const int4*>(&g_deg[idx]);
        v[0] = d.x; v[1] = d.y; v[2] = d.z; v[3] = d.w;
    } else {
#pragma unroll
        for (int k = 0; k < 4; k++) v[k] = (idx + k < NN) ? g_deg[idx + k] : 0;
    }
    const int tot = v[0] + v[1] + v[2] + v[3];

    int x = tot;
#pragma unroll
    for (int o = 1; o < 32; o <<= 1) {
        int t = __shfl_up_sync(0xffffffffu, x, o);
        if (lane >= o) x += t;
    }
    if (lane == 31) wsum[wid] = x;
    __syncthreads();
    if (threadIdx.x < 32) {
        int w = (threadIdx.x < 8) ? wsum[threadIdx.x] : 0;
#pragma unroll
        for (int o = 1; o < 8; o <<= 1) {
            int t = __shfl_up_sync(0xffffffffu, w, o);
            if (threadIdx.x >= (unsigned)o) w += t;
        }
        if (threadIdx.x < 8) wsum[threadIdx.x] = w;
    }
    __syncthreads();

    if (threadIdx.x == 0)
        ((volatile int*)g_flagval)[bid] = wsum[7] + 1;

    int pre = 0;
    if ((int)threadIdx.x < bid) {
        volatile int* fv = g_flagval;
        int f;
        do { f = fv[threadIdx.x]; } while (f == 0);
        pre = f - 1;
    }
#pragma unroll
    for (int o = 16; o > 0; o >>= 1) pre += __shfl_down_sync(0xffffffffu, pre, o);
    if (lane == 0) wred[wid] = pre;
    __syncthreads();
    if (threadIdx.x < 32) {
        int r = (threadIdx.x < 8) ? wred[threadIdx.x] : 0;
#pragma unroll
        for (int o = 4; o > 0; o >>= 1) r += __shfl_down_sync(0xffffffffu, r, o);
        if (threadIdx.x == 0) s_base = r;
    }
    __syncthreads();

    int run = s_base + ((wid > 0) ? wsum[wid - 1] : 0) + (x - tot);
#pragma unroll
    for (int k = 0; k < 4; k++) {
        if (idx + k < NN) g_off[idx + k] = run;
        run += v[k];
    }
}

// ============================================================
// K4: CSR scatter — atomic-free. Slot = off[dst] + rank.
// ============================================================
__global__ __launch_bounds__(256) void k_scatter(const int* __restrict__ src,
                                                 const int* __restrict__ dst) {
    int t = blockIdx.x * blockDim.x + threadIdx.x;
    if (t * 4 >= NE) return;
    int4 s4 = reinterpret_cast<const int4*>(src)[t];
    int4 d4 = reinterpret_cast<const int4*>(dst)[t];
    int4 r4 = reinterpret_cast<const int4*>(g_rank)[t];
    int ss[4] = {s4.x, s4.y, s4.z, s4.w};
    int dd[4] = {d4.x, d4.y, d4.z, d4.w};
    int rr[4] = {r4.x, r4.y, r4.z, r4.w};

    int o[4];
#pragma unroll
    for (int k = 0; k < 4; k++) o[k] = __ldg(&g_off[dd[k]]);
#pragma unroll
    for (int k = 0; k < 4; k++) g_csrc[o[k] + rr[k]] = ss[k];
}

// ============================================================
// K5: per-dst gather-reduce, half-warp/float4, 16 edges/warp
//     iteration (8 per half, z[8] float4 in flight per lane).
//     Halves combine via shfl_xor(16); float4 coalesced output.
//     e = leaky(ssrc[s] + sdst[node]); softmax without max shift
//     (scores O(1); shift cancels in ratio) + weighted sum + elu.
// ============================================================
__global__ __launch_bounds__(256) void k_aggr(float* __restrict__ out) {
    int node = blockIdx.x * 8 + (threadIdx.x >> 5);
    int lane = threadIdx.x & 31;
    int half = lane >> 4;        // 0 or 1: which edge subset
    int hl   = lane & 15;        // float4 index within row (cols 4*hl..4*hl+3)
    if (node >= NN) return;

    float4* orow = reinterpret_cast<float4*>(out + (size_t)node * OUTD);

    int start = g_off[node];
    int dg    = g_deg[node];
    if (dg == 0) {
        if (half == 0) orow[hl] = make_float4(0.f, 0.f, 0.f, 0.f);
        return;
    }
    const float sd = g_sdst[node];

    float4 acc = make_float4(0.f, 0.f, 0.f, 0.f);
    float denom = 0.f;

    int j = 0;
    // 16 edges per warp iteration: 8 per half, all loads in flight
    for (; j + 15 < dg; j += 16) {
        int e0 = start + j + half * 8;
        int s[8];
#pragma unroll
        for (int k = 0; k < 8; k++) s[k] = g_csrc[e0 + k];
        float v[8];
#pragma unroll
        for (int k = 0; k < 8; k++) v[k] = __ldg(&g_ssrc[s[k]]) + sd;
        float4 z[8];
#pragma unroll
        for (int k = 0; k < 8; k++)
            z[k] = __ldg(&reinterpret_cast<const float4*>(&g_z[(size_t)s[k] * OUTD])[hl]);
#pragma unroll
        for (int k = 0; k < 8; k++) {
            float x = __expf(v[k] > 0.f ? v[k] : 0.01f * v[k]);
            denom += x;
            acc.x += x * z[k].x; acc.y += x * z[k].y;
            acc.z += x * z[k].z; acc.w += x * z[k].w;
        }
    }
    // 8 edges: 4 per half
    for (; j + 7 < dg; j += 8) {
        int e0 = start + j + half * 4;
        int s[4];
#pragma unroll
        for (int k = 0; k < 4; k++) s[k] = g_csrc[e0 + k];
        float v[4];
#pragma unroll
        for (int k = 0; k < 4; k++) v[k] = __ldg(&g_ssrc[s[k]]) + sd;
        float4 z[4];
#pragma unroll
        for (int k = 0; k < 4; k++)
            z[k] = __ldg(&reinterpret_cast<const float4*>(&g_z[(size_t)s[k] * OUTD])[hl]);
#pragma unroll
        for (int k = 0; k < 4; k++) {
            float x = __expf(v[k] > 0.f ? v[k] : 0.01f * v[k]);
            denom += x;
            acc.x += x * z[k].x; acc.y += x * z[k].y;
            acc.z += x * z[k].z; acc.w += x * z[k].w;
        }
    }
    // pairs: one edge per half
    for (; j + 1 < dg; j += 2) {
        int s = g_csrc[start + j + half];
        float v = __ldg(&g_ssrc[s]) + sd;
        float x = __expf(v > 0.f ? v : 0.01f * v);
        float4 z = __ldg(&reinterpret_cast<const float4*>(&g_z[(size_t)s * OUTD])[hl]);
        denom += x;
        acc.x += x * z.x; acc.y += x * z.y; acc.z += x * z.z; acc.w += x * z.w;
    }
    // last odd edge: half 0 only
    if (j < dg && half == 0) {
        int s = g_csrc[start + j];
        float v = __ldg(&g_ssrc[s]) + sd;
        float x = __expf(v > 0.f ? v : 0.01f * v);
        float4 z = __ldg(&reinterpret_cast<const float4*>(&g_z[(size_t)s * OUTD])[hl]);
        denom += x;
        acc.x += x * z.x; acc.y += x * z.y; acc.z += x * z.z; acc.w += x * z.w;
    }

    // combine halves: lanes l and l^16 hold the same columns
    acc.x += __shfl_xor_sync(0xffffffffu, acc.x, 16);
    acc.y += __shfl_xor_sync(0xffffffffu, acc.y, 16);
    acc.z += __shfl_xor_sync(0xffffffffu, acc.z, 16);
    acc.w += __shfl_xor_sync(0xffffffffu, acc.w, 16);
    denom += __shfl_xor_sync(0xffffffffu, denom, 16);

    float inv = 1.0f / denom;     // denom > 0 (all terms > 0)
    float o0 = acc.x * inv, o1 = acc.y * inv, o2 = acc.z * inv, o3 = acc.w * inv;
    if (half == 0) {
        orow[hl] = make_float4(o0 > 0.f ? o0 : (__expf(o0) - 1.f),
                               o1 > 0.f ? o1 : (__expf(o1) - 1.f),
                               o2 > 0.f ? o2 : (__expf(o2) - 1.f),
                               o3 > 0.f ? o3 : (__expf(o3) - 1.f));
    }
}

// ============================================================
// Fork/join: gemm on the main (capture) stream; CSR build on a
// high-priority side stream; join before aggr.
// ============================================================
extern "C" void kernel_launch(void* const* d_in, const int* in_sizes, int n_in,
                              void* d_out, int out_size) {
    const float* h   = (const float*)d_in[0];
    const int*   src = (const int*)d_in[1];
    const int*   dst = (const int*)d_in[2];
    const float* W   = (const float*)d_in[3];
    const float* a   = (const float*)d_in[4];
    float* out = (float*)d_out;

    static cudaStream_t s_side = nullptr;
    static cudaEvent_t  ev_fork = nullptr, ev_join = nullptr;
    if (s_side == nullptr) {
        int lo, hi;
        cudaDeviceGetStreamPriorityRange(&lo, &hi);
        cudaStreamCreateWithPriority(&s_side, cudaStreamNonBlocking, hi);
        cudaEventCreateWithFlags(&ev_fork, cudaEventDisableTiming);
        cudaEventCreateWithFlags(&ev_join, cudaEventDisableTiming);
    }

    // fork side stream off the main (capture) stream
    cudaEventRecord(ev_fork, 0);
    cudaStreamWaitEvent(s_side, ev_fork, 0);

    // main stream: GEMM + fused scores (FFMA-bound)
    k_gemm<<<(NN + 127) / 128, 256>>>(h, W, a);

    // side stream: CSR build (memory/atomic-bound, independent of gemm)
    k_zero   <<<(NN / 4 + 255) / 256, 256, 0, s_side>>>();
    k_hist   <<<(NE / 4 + 255) / 256, 256, 0, s_side>>>(dst);
    k_scan   <<<NBLK, 256, 0, s_side>>>();
    k_scatter<<<(NE / 4 + 255) / 256, 256, 0, s_side>>>(src, dst);

    // join
    cudaEventRecord(ev_join, s_side);
    cudaStreamWaitEvent(0, ev_join, 0);

    k_aggr<<<(NN + 7) / 8, 256>>>(out);
}

// round 15
// speedup vs baseline: 1.8058x; 1.0016x over previous
#include <cuda_runtime.h>
#include <cuda_fp16.h>
#include <math_constants.h>

#define NN 100000
#define NE 1600000
#define IND 128
#define OUTD 64

#define SCAN_ELEMS 1024                       // per block (256 thr x 4)
#define NBLK ((NN + SCAN_ELEMS - 1) / SCAN_ELEMS)   // 98

// ---- scratch (static device globals; no allocation) ----
__device__ __align__(16) __half g_zh[(size_t)NN * OUTD];   // 12.8 MB (fp16 features)
__device__ __align__(16) float g_ssrc[NN];
__device__ __align__(16) float g_sdst[NN];
__device__ __align__(16) int   g_deg[NN];
__device__ __align__(16) int   g_off[NN];
__device__ __align__(16) int   g_rank[NE];                 // 6.4 MB
__device__ __align__(16) int   g_csrc[NE];                 // 6.4 MB
__device__ int g_flagval[NBLK];                            // scan lookback: total+1, 0=unpublished

// ============================================================
// K1: z = h @ W^T  (128x64 tile, 8x4/thread). Scores s_src/s_dst
//     computed from fp32 accumulators (exact); z stored fp16.
// ============================================================
__global__ __launch_bounds__(256) void k_gemm(const float* __restrict__ h,
                                              const float* __restrict__ W,
                                              const float* __restrict__ a) {
    __shared__ __align__(16) float hs[32][132];  // hs[k][node] (128 + pad)
    __shared__ __align__(16) float ws[32][68];   // ws[k][out] = W[out][k]

    const int tx = threadIdx.x & 15;        // out tile (x4)
    const int ty = threadIdx.x >> 4;        // node tile (x8)
    const int node0 = blockIdx.x * 128;

    float acc[8][4];
#pragma unroll
    for (int i = 0; i < 8; i++)
#pragma unroll
        for (int j = 0; j < 4; j++) acc[i][j] = 0.f;

    for (int k0 = 0; k0 < IND; k0 += 32) {
        // load h tile: 128 rows x 8 float4; 2 threads/row, 4 float4 each
        {
            const int r  = threadIdx.x >> 1;             // 0..127
            const int q0 = (threadIdx.x & 1) * 4;        // float4 index 0 or 4
            int gn = node0 + r;
            float4 v[4];
            if (gn < NN) {
                const float4* hp = reinterpret_cast<const float4*>(h + (size_t)gn * IND + k0) + q0;
#pragma unroll
                for (int q = 0; q < 4; q++) v[q] = hp[q];
            } else {
#pragma unroll
                for (int q = 0; q < 4; q++) v[q] = make_float4(0.f, 0.f, 0.f, 0.f);
            }
#pragma unroll
            for (int q = 0; q < 4; q++) {
                int kk = (q0 + q) * 4;
                hs[kk + 0][r] = v[q].x; hs[kk + 1][r] = v[q].y;
                hs[kk + 2][r] = v[q].z; hs[kk + 3][r] = v[q].w;
            }
        }
        // load W tile: 64 rows x 8 float4; 4 threads/row, 2 float4 each
        {
            const int r  = threadIdx.x >> 2;             // 0..63
            const int q0 = (threadIdx.x & 3) * 2;        // float4 index
            const float4* wp = reinterpret_cast<const float4*>(W + (size_t)r * IND + k0) + q0;
            float4 w0 = wp[0], w1 = wp[1];
            int kk = q0 * 4;
            ws[kk + 0][r] = w0.x; ws[kk + 1][r] = w0.y; ws[kk + 2][r] = w0.z; ws[kk + 3][r] = w0.w;
            ws[kk + 4][r] = w1.x; ws[kk + 5][r] = w1.y; ws[kk + 6][r] = w1.z; ws[kk + 7][r] = w1.w;
        }
        __syncthreads();
#pragma unroll
        for (int kk = 0; kk < 32; kk++) {
            float4 a0 = *reinterpret_cast<const float4*>(&hs[kk][ty * 8]);
            float4 a1 = *reinterpret_cast<const float4*>(&hs[kk][ty * 8 + 4]);
            float4 bv = *reinterpret_cast<const float4*>(&ws[kk][tx * 4]);
            float aa[8] = {a0.x, a0.y, a0.z, a0.w, a1.x, a1.y, a1.z, a1.w};
            float bb[4] = {bv.x, bv.y, bv.z, bv.w};
#pragma unroll
            for (int i = 0; i < 8; i++)
#pragma unroll
                for (int j = 0; j < 4; j++) acc[i][j] += aa[i] * bb[j];
        }
        __syncthreads();
    }

    // store z tile as fp16 (8B per thread per row, coalesced)
#pragma unroll
    for (int i = 0; i < 8; i++) {
        int gn = node0 + ty * 8 + i;
        if (gn < NN) {
            union { uint2 u; __half2 h2[2]; } p;
            p.h2[0] = __floats2half2_rn(acc[i][0], acc[i][1]);
            p.h2[1] = __floats2half2_rn(acc[i][2], acc[i][3]);
            *reinterpret_cast<uint2*>(&g_zh[(size_t)gn * OUTD + tx * 4]) = p.u;
        }
    }

    // fused score epilogue from fp32 accs: width-16 shuffle reduce
    float as[4], ad[4];
#pragma unroll
    for (int j = 0; j < 4; j++) {
        as[j] = __ldg(&a[tx * 4 + j]);
        ad[j] = __ldg(&a[64 + tx * 4 + j]);
    }
#pragma unroll
    for (int i = 0; i < 8; i++) {
        float ps = acc[i][0] * as[0] + acc[i][1] * as[1] + acc[i][2] * as[2] + acc[i][3] * as[3];
        float pd = acc[i][0] * ad[0] + acc[i][1] * ad[1] + acc[i][2] * ad[2] + acc[i][3] * ad[3];
#pragma unroll
        for (int o = 8; o > 0; o >>= 1) {
            ps += __shfl_down_sync(0xffffffffu, ps, o, 16);
            pd += __shfl_down_sync(0xffffffffu, pd, o, 16);
        }
        if (tx == 0) {
            int gn = node0 + ty * 8 + i;
            if (gn < NN) { g_ssrc[gn] = ps; g_sdst[gn] = pd; }
        }
    }
}

// ============================================================
// K0 (side stream): zero deg + scan flags (int4 stores)
// ============================================================
__global__ __launch_bounds__(256) void k_zero() {
    int t = blockIdx.x * blockDim.x + threadIdx.x;
    if (t * 4 < NN)
        reinterpret_cast<int4*>(g_deg)[t] = make_int4(0, 0, 0, 0);
    if (t < NBLK) g_flagval[t] = 0;
}

// ============================================================
// K2: dst-degree histogram; atomic return value = rank
// ============================================================
__global__ __launch_bounds__(256) void k_hist(const int* __restrict__ dst) {
    int t = blockIdx.x * blockDim.x + threadIdx.x;
    if (t * 4 >= NE) return;
    int4 d4 = reinterpret_cast<const int4*>(dst)[t];
    int4 r4;
    r4.x = atomicAdd(&g_deg[d4.x], 1);
    r4.y = atomicAdd(&g_deg[d4.y], 1);
    r4.z = atomicAdd(&g_deg[d4.z], 1);
    r4.w = atomicAdd(&g_deg[d4.w], 1);
    reinterpret_cast<int4*>(g_rank)[t] = r4;  // coalesced
}

// ============================================================
// K3: single-kernel exclusive scan with parallel lookback.
// ============================================================
__global__ __launch_bounds__(256) void k_scan() {
    __shared__ int wsum[8];
    __shared__ int wred[8];
    __shared__ int s_base;
    const int bid  = blockIdx.x;
    const int lane = threadIdx.x & 31, wid = threadIdx.x >> 5;
    const int idx  = bid * SCAN_ELEMS + threadIdx.x * 4;

    int v[4];
    if (idx + 3 < NN) {
        int4 d = *reinterpret_cast<const int4*>(&g_deg[idx]);
        v[0] = d.x; v[1] = d.y; v[2] = d.z; v[3] = d.w;
    } else {
#pragma unroll
        for (int k = 0; k < 4; k++) v[k] = (idx + k < NN) ? g_deg[idx + k] : 0;
    }
    const int tot = v[0] + v[1] + v[2] + v[3];

    int x = tot;
#pragma unroll
    for (int o = 1; o < 32; o <<= 1) {
        int t = __shfl_up_sync(0xffffffffu, x, o);
        if (lane >= o) x += t;
    }
    if (lane == 31) wsum[wid] = x;
    __syncthreads();
    if (threadIdx.x < 32) {
        int w = (threadIdx.x < 8) ? wsum[threadIdx.x] : 0;
#pragma unroll
        for (int o = 1; o < 8; o <<= 1) {
            int t = __shfl_up_sync(0xffffffffu, w, o);
            if (threadIdx.x >= (unsigned)o) w += t;
        }
        if (threadIdx.x < 8) wsum[threadIdx.x] = w;
    }
    __syncthreads();

    if (threadIdx.x == 0)
        ((volatile int*)g_flagval)[bid] = wsum[7] + 1;

    int pre = 0;
    if ((int)threadIdx.x < bid) {
        volatile int* fv = g_flagval;
        int f;
        do { f = fv[threadIdx.x]; } while (f == 0);
        pre = f - 1;
    }
#pragma unroll
    for (int o = 16; o > 0; o >>= 1) pre += __shfl_down_sync(0xffffffffu, pre, o);
    if (lane == 0) wred[wid] = pre;
    __syncthreads();
    if (threadIdx.x < 32) {
        int r = (threadIdx.x < 8) ? wred[threadIdx.x] : 0;
#pragma unroll
        for (int o = 4; o > 0; o >>= 1) r += __shfl_down_sync(0xffffffffu, r, o);
        if (threadIdx.x == 0) s_base = r;
    }
    __syncthreads();

    int run = s_base + ((wid > 0) ? wsum[wid - 1] : 0) + (x - tot);
#pragma unroll
    for (int k = 0; k < 4; k++) {
        if (idx + k < NN) g_off[idx + k] = run;
        run += v[k];
    }
}

// ============================================================
// K4: CSR scatter — atomic-free. Slot = off[dst] + rank.
// ============================================================
__global__ __launch_bounds__(256) void k_scatter(const int* __restrict__ src,
                                                 const int* __restrict__ dst) {
    int t = blockIdx.x * blockDim.x + threadIdx.x;
    if (t * 4 >= NE) return;
    int4 s4 = reinterpret_cast<const int4*>(src)[t];
    int4 d4 = reinterpret_cast<const int4*>(dst)[t];
    int4 r4 = reinterpret_cast<const int4*>(g_rank)[t];
    int ss[4] = {s4.x, s4.y, s4.z, s4.w};
    int dd[4] = {d4.x, d4.y, d4.z, d4.w};
    int rr[4] = {r4.x, r4.y, r4.z, r4.w};

    int o[4];
#pragma unroll
    for (int k = 0; k < 4; k++) o[k] = __ldg(&g_off[dd[k]]);
#pragma unroll
    for (int k = 0; k < 4; k++) g_csrc[o[k] + rr[k]] = ss[k];
}

// ============================================================
// K5: per-dst gather-reduce over fp16 z rows (128B/row).
//     Half-warp per edge-subset; lane hl loads one uint2 (4
//     halves = cols 4*hl..4*hl+3). 16 edges/warp iteration.
//     Softmax weights computed in fp32 from exact scores.
// ============================================================
__global__ __launch_bounds__(256) void k_aggr(float* __restrict__ out) {
    int node = blockIdx.x * 8 + (threadIdx.x >> 5);
    int lane = threadIdx.x & 31;
    int half = lane >> 4;        // 0 or 1: which edge subset
    int hl   = lane & 15;        // uint2 index within row (cols 4*hl..4*hl+3)
    if (node >= NN) return;

    float4* orow = reinterpret_cast<float4*>(out + (size_t)node * OUTD);

    int start = g_off[node];
    int dg    = g_deg[node];
    if (dg == 0) {
        if (half == 0) orow[hl] = make_float4(0.f, 0.f, 0.f, 0.f);
        return;
    }
    const float sd = g_sdst[node];

    float4 acc = make_float4(0.f, 0.f, 0.f, 0.f);
    float denom = 0.f;

    int j = 0;
    // 16 edges per warp iteration: 8 per half, all loads in flight
    for (; j + 15 < dg; j += 16) {
        int e0 = start + j + half * 8;
        int s[8];
#pragma unroll
        for (int k = 0; k < 8; k++) s[k] = g_csrc[e0 + k];
        float v[8];
#pragma unroll
        for (int k = 0; k < 8; k++) v[k] = __ldg(&g_ssrc[s[k]]) + sd;
        uint2 z[8];
#pragma unroll
        for (int k = 0; k < 8; k++)
            z[k] = __ldg(&reinterpret_cast<const uint2*>(&g_zh[(size_t)s[k] * OUTD])[hl]);
#pragma unroll
        for (int k = 0; k < 8; k++) {
            float x = __expf(v[k] > 0.f ? v[k] : 0.01f * v[k]);
            float2 fa = __half22float2(*reinterpret_cast<const __half2*>(&z[k].x));
            float2 fb = __half22float2(*reinterpret_cast<const __half2*>(&z[k].y));
            denom += x;
            acc.x += x * fa.x; acc.y += x * fa.y;
            acc.z += x * fb.x; acc.w += x * fb.y;
        }
    }
    // 8 edges: 4 per half
    for (; j + 7 < dg; j += 8) {
        int e0 = start + j + half * 4;
        int s[4];
#pragma unroll
        for (int k = 0; k < 4; k++) s[k] = g_csrc[e0 + k];
        float v[4];
#pragma unroll
        for (int k = 0; k < 4; k++) v[k] = __ldg(&g_ssrc[s[k]]) + sd;
        uint2 z[4];
#pragma unroll
        for (int k = 0; k < 4; k++)
            z[k] = __ldg(&reinterpret_cast<const uint2*>(&g_zh[(size_t)s[k] * OUTD])[hl]);
#pragma unroll
        for (int k = 0; k < 4; k++) {
            float x = __expf(v[k] > 0.f ? v[k] : 0.01f * v[k]);
            float2 fa = __half22float2(*reinterpret_cast<const __half2*>(&z[k].x));
            float2 fb = __half22float2(*reinterpret_cast<const __half2*>(&z[k].y));
            denom += x;
            acc.x += x * fa.x; acc.y += x * fa.y;
            acc.z += x * fb.x; acc.w += x * fb.y;
        }
    }
    // pairs: one edge per half
    for (; j + 1 < dg; j += 2) {
        int s = g_csrc[start + j + half];
        float v = __ldg(&g_ssrc[s]) + sd;
        float x = __expf(v > 0.f ? v : 0.01f * v);
        uint2 z = __ldg(&reinterpret_cast<const uint2*>(&g_zh[(size_t)s * OUTD])[hl]);
        float2 fa = __half22float2(*reinterpret_cast<const __half2*>(&z.x));
        float2 fb = __half22float2(*reinterpret_cast<const __half2*>(&z.y));
        denom += x;
        acc.x += x * fa.x; acc.y += x * fa.y;
        acc.z += x * fb.x; acc.w += x * fb.y;
    }
    // last odd edge: half 0 only
    if (j < dg && half == 0) {
        int s = g_csrc[start + j];
        float v = __ldg(&g_ssrc[s]) + sd;
        float x = __expf(v > 0.f ? v : 0.01f * v);
        uint2 z = __ldg(&reinterpret_cast<const uint2*>(&g_zh[(size_t)s * OUTD])[hl]);
        float2 fa = __half22float2(*reinterpret_cast<const __half2*>(&z.x));
        float2 fb = __half22float2(*reinterpret_cast<const __half2*>(&z.y));
        denom += x;
        acc.x += x * fa.x; acc.y += x * fa.y;
        acc.z += x * fb.x; acc.w += x * fb.y;
    }

    // combine halves: lanes l and l^16 hold the same columns
    acc.x += __shfl_xor_sync(0xffffffffu, acc.x, 16);
    acc.y += __shfl_xor_sync(0xffffffffu, acc.y, 16);
    acc.z += __shfl_xor_sync(0xffffffffu, acc.z, 16);
    acc.w += __shfl_xor_sync(0xffffffffu, acc.w, 16);
    denom += __shfl_xor_sync(0xffffffffu, denom, 16);

    float inv = 1.0f / denom;     // denom > 0 (all terms > 0)
    float o0 = acc.x * inv, o1 = acc.y * inv, o2 = acc.z * inv, o3 = acc.w * inv;
    if (half == 0) {
        orow[hl] = make_float4(o0 > 0.f ? o0 : (__expf(o0) - 1.f),
                               o1 > 0.f ? o1 : (__expf(o1) - 1.f),
                               o2 > 0.f ? o2 : (__expf(o2) - 1.f),
                               o3 > 0.f ? o3 : (__expf(o3) - 1.f));
    }
}

// ============================================================
// Fork/join: gemm on the main (capture) stream; CSR build on a
// high-priority side stream; join before aggr.
// ============================================================
extern "C" void kernel_launch(void* const* d_in, const int* in_sizes, int n_in,
                              void* d_out, int out_size) {
    const float* h   = (const float*)d_in[0];
    const int*   src = (const int*)d_in[1];
    const int*   dst = (const int*)d_in[2];
    const float* W   = (const float*)d_in[3];
    const float* a   = (const float*)d_in[4];
    float* out = (float*)d_out;

    static cudaStream_t s_side = nullptr;
    static cudaEvent_t  ev_fork = nullptr, ev_join = nullptr;
    if (s_side == nullptr) {
        int lo, hi;
        cudaDeviceGetStreamPriorityRange(&lo, &hi);
        cudaStreamCreateWithPriority(&s_side, cudaStreamNonBlocking, hi);
        cudaEventCreateWithFlags(&ev_fork, cudaEventDisableTiming);
        cudaEventCreateWithFlags(&ev_join, cudaEventDisableTiming);
    }

    // fork side stream off the main (capture) stream
    cudaEventRecord(ev_fork, 0);
    cudaStreamWaitEvent(s_side, ev_fork, 0);

    // main stream: GEMM + fused scores (FFMA-bound)
    k_gemm<<<(NN + 127) / 128, 256>>>(h, W, a);

    // side stream: CSR build (memory/atomic-bound, independent of gemm)
    k_zero   <<<(NN / 4 + 255) / 256, 256, 0, s_side>>>();
    k_hist   <<<(NE / 4 + 255) / 256, 256, 0, s_side>>>(dst);
    k_scan   <<<NBLK, 256, 0, s_side>>>();
    k_scatter<<<(NE / 4 + 255) / 256, 256, 0, s_side>>>(src, dst);

    // join
    cudaEventRecord(ev_join, s_side);
    cudaStreamWaitEvent(0, ev_join, 0);

    k_aggr<<<(NN + 7) / 8, 256>>>(out);
}